// round 6
// baseline (speedup 1.0000x reference)
#include <cuda_runtime.h>
#include <cuda_bf16.h>
#include <math.h>
#include <stdint.h>

// Problem constants
#define Bb   64
#define Ss   128
#define Hh   768
#define Aa   512
#define COn  100
#define TnK  5
#define T1K  6
#define Nn   64
#define SCn  12
#define MSZ  (Bb*Ss*Hh)      // 6291456
#define M1   (Bb*Ss)         // 8192

#define NG_PAD 2432
#define NA_PAD 1280
#define MG     (TnK*M1)      // 40960

// ---------------------------------------------------------------------------
// Scratch (static device globals — allocation-free)
// ---------------------------------------------------------------------------
__device__ __nv_bfloat16 g_xh[MSZ],  g_xl[MSZ];
__device__ __nv_bfloat16 g_f1h[T1K * Aa * Hh], g_f1l[T1K * Aa * Hh];
__device__ __nv_bfloat16 g_f2h[T1K * Hh * Aa], g_f2l[T1K * Hh * Aa];
__device__ __nv_bfloat16 g_h1h[T1K * M1 * Aa], g_h1l[T1K * M1 * Aa];
__device__ float         g_h2[T1K * MSZ];
__device__ __nv_bfloat16 g_sqh[T1K * MSZ], g_sql[T1K * MSZ];
__device__ __nv_bfloat16 g_Wgh[NG_PAD * Hh], g_Wgl[NG_PAD * Hh];
__device__ __nv_bfloat16 g_Wah[NA_PAD * Hh], g_Wal[NA_PAD * Hh];
__device__ float g_Yg[(long)MG * NG_PAD];
__device__ float g_Ya[(long)M1 * NA_PAD];
__device__ float g_aspf[Bb * 3 * COn];
__device__ float g_asp[Bb * COn];
__device__ float g_z[TnK * Bb * 3 * COn];
__device__ float g_priors[Nn * Bb * T1K * SCn];
__device__ float g_vote[Nn * Bb * SCn];

// ---------------------------------------------------------------------------
// helpers
// ---------------------------------------------------------------------------
__device__ __forceinline__ void mma16816(float* c, const uint32_t* a, const uint32_t* b)
{
    asm volatile(
        "mma.sync.aligned.m16n8k16.row.col.f32.bf16.bf16.f32 "
        "{%0,%1,%2,%3}, {%4,%5,%6,%7}, {%8,%9}, {%0,%1,%2,%3};"
        : "+f"(c[0]), "+f"(c[1]), "+f"(c[2]), "+f"(c[3])
        : "r"(a[0]), "r"(a[1]), "r"(a[2]), "r"(a[3]), "r"(b[0]), "r"(b[1]));
}

__device__ __forceinline__ void split2(float x0, float x1, uint32_t& hp, uint32_t& lp)
{
    asm("cvt.rn.bf16x2.f32 %0, %1, %2;" : "=r"(hp) : "f"(x1), "f"(x0));
    float h0 = __uint_as_float(hp << 16);
    float h1 = __uint_as_float(hp & 0xffff0000u);
    float r0 = x0 - h0, r1 = x1 - h1;
    asm("cvt.rn.bf16x2.f32 %0, %1, %2;" : "=r"(lp) : "f"(r1), "f"(r0));
}

__device__ __forceinline__ void cp16(void* sdst, const void* gsrc)
{
    uint32_t s = (uint32_t)__cvta_generic_to_shared(sdst);
    asm volatile("cp.async.cg.shared.global [%0], [%1], 16;" :: "r"(s), "l"(gsrc));
}
#define CP_COMMIT() asm volatile("cp.async.commit_group;" ::: "memory")
#define CP_WAIT0()  asm volatile("cp.async.wait_group 0;" ::: "memory")

// ===========================================================================
// Warp-MMA GEMM, pre-split bf16 operands, cp.async pipeline.
// Inner loop reordered so each accumulator is revisited only every 8 MMAs
// (break the hi/lo RAW chain).
// OUT: 0 = fp32 plain, 1 = fp32 bias+relu, 2 = bf16 hi/lo bias+relu
// ===========================================================================
#define KC       32
#define RSTR     40
#define MAT_ELE  (128 * RSTR)           // 5120
#define STG_ELE  (4 * MAT_ELE)
#define SMEM_REQ (2 * STG_ELE * 2)      // 81920 bytes

template<int OUT>
__global__ void __launch_bounds__(256, 2)
mma_gemm(const __nv_bfloat16* __restrict__ Ah, const __nv_bfloat16* __restrict__ Al,
         const __nv_bfloat16* __restrict__ Bh, const __nv_bfloat16* __restrict__ Bl,
         const float* __restrict__ bias,
         float* __restrict__ Cf, __nv_bfloat16* __restrict__ Chi, __nv_bfloat16* __restrict__ Clo,
         int N, int Kd, long sA, long sW, long sB, long sC)
{
    extern __shared__ __nv_bfloat16 sm[];
    long zo = blockIdx.z * sA;
    Ah += zo; Al += zo;
    zo = blockIdx.z * sW;
    Bh += zo; Bl += zo;
    if (OUT) bias += blockIdx.z * sB;
    long co = blockIdx.z * sC;

    int m0 = blockIdx.y * 128, n0 = blockIdx.x * 128;
    int tid = threadIdx.x, lane = tid & 31, wid = tid >> 5;
    int wm = wid >> 2, wn = wid & 3;
    int gid = lane >> 2, tig = lane & 3;

    int crow = tid >> 2, cch = (tid & 3) * 8;

    auto issue = [&](int c, int st) {
        __nv_bfloat16* base = sm + st * STG_ELE;
        int k0 = c * KC;
        #pragma unroll
        for (int r = 0; r < 2; r++) {
            int row = crow + r * 64;
            long ga = (long)(m0 + row) * Kd + k0 + cch;
            long gb = (long)(n0 + row) * Kd + k0 + cch;
            int so = row * RSTR + cch;
            cp16(base + so,               Ah + ga);
            cp16(base + MAT_ELE + so,     Al + ga);
            cp16(base + 2 * MAT_ELE + so, Bh + gb);
            cp16(base + 3 * MAT_ELE + so, Bl + gb);
        }
        CP_COMMIT();
    };

    float acc[4][4][4] = {};
    int nch = Kd / KC;

    issue(0, 0);

    for (int c = 0; c < nch; c++) {
        CP_WAIT0();
        __syncthreads();
        if (c + 1 < nch) issue(c + 1, (c + 1) & 1);

        const __nv_bfloat16* Ahs = sm + (c & 1) * STG_ELE;
        const __nv_bfloat16* Als = Ahs + MAT_ELE;
        const __nv_bfloat16* Bhs = Als + MAT_ELE;
        const __nv_bfloat16* Bls = Bhs + MAT_ELE;

        #pragma unroll
        for (int kk = 0; kk < KC; kk += 16) {
            uint32_t bh[4][2], bl[4][2];
            #pragma unroll
            for (int nt = 0; nt < 4; nt++) {
                int off = (wn * 32 + nt * 8 + gid) * RSTR + kk + tig * 2;
                bh[nt][0] = *(const uint32_t*)(Bhs + off);
                bh[nt][1] = *(const uint32_t*)(Bhs + off + 8);
                bl[nt][0] = *(const uint32_t*)(Bls + off);
                bl[nt][1] = *(const uint32_t*)(Bls + off + 8);
            }
            // process mt in pairs; within a pair, sweep each term class across
            // (mt2, nt) so a given acc is revisited only every 8 MMAs.
            #pragma unroll
            for (int mp = 0; mp < 2; mp++) {
                uint32_t ah[2][4], al[2][4];
                #pragma unroll
                for (int m2 = 0; m2 < 2; m2++) {
                    int mt = mp * 2 + m2;
                    int off = (wm * 64 + mt * 16 + gid) * RSTR + kk + tig * 2;
                    ah[m2][0] = *(const uint32_t*)(Ahs + off);
                    ah[m2][1] = *(const uint32_t*)(Ahs + off + 8 * RSTR);
                    ah[m2][2] = *(const uint32_t*)(Ahs + off + 8);
                    ah[m2][3] = *(const uint32_t*)(Ahs + off + 8 * RSTR + 8);
                    al[m2][0] = *(const uint32_t*)(Als + off);
                    al[m2][1] = *(const uint32_t*)(Als + off + 8 * RSTR);
                    al[m2][2] = *(const uint32_t*)(Als + off + 8);
                    al[m2][3] = *(const uint32_t*)(Als + off + 8 * RSTR + 8);
                }
                #pragma unroll
                for (int m2 = 0; m2 < 2; m2++)
                    #pragma unroll
                    for (int nt = 0; nt < 4; nt++)
                        mma16816(acc[mp * 2 + m2][nt], ah[m2], bh[nt]);
                #pragma unroll
                for (int m2 = 0; m2 < 2; m2++)
                    #pragma unroll
                    for (int nt = 0; nt < 4; nt++)
                        mma16816(acc[mp * 2 + m2][nt], ah[m2], bl[nt]);
                #pragma unroll
                for (int m2 = 0; m2 < 2; m2++)
                    #pragma unroll
                    for (int nt = 0; nt < 4; nt++)
                        mma16816(acc[mp * 2 + m2][nt], al[m2], bh[nt]);
            }
        }
        __syncthreads();
    }

    // epilogue
    #pragma unroll
    for (int mt = 0; mt < 4; mt++) {
        long m = m0 + wm * 64 + mt * 16 + gid;
        #pragma unroll
        for (int nt = 0; nt < 4; nt++) {
            int col = n0 + wn * 32 + nt * 8 + tig * 2;
            float b0 = 0.f, b1 = 0.f;
            if (OUT) { b0 = bias[col]; b1 = bias[col + 1]; }
            float v00 = acc[mt][nt][0] + b0, v01 = acc[mt][nt][1] + b1;
            float v10 = acc[mt][nt][2] + b0, v11 = acc[mt][nt][3] + b1;
            if (OUT) {
                v00 = fmaxf(v00, 0.f); v01 = fmaxf(v01, 0.f);
                v10 = fmaxf(v10, 0.f); v11 = fmaxf(v11, 0.f);
            }
            if (OUT == 2) {
                uint32_t hp, lp;
                split2(v00, v01, hp, lp);
                *(uint32_t*)(Chi + co + m * N + col) = hp;
                *(uint32_t*)(Clo + co + m * N + col) = lp;
                split2(v10, v11, hp, lp);
                *(uint32_t*)(Chi + co + (m + 8) * N + col) = hp;
                *(uint32_t*)(Clo + co + (m + 8) * N + col) = lp;
            } else {
                *(float2*)(Cf + co + m * N + col)       = make_float2(v00, v01);
                *(float2*)(Cf + co + (m + 8) * N + col) = make_float2(v10, v11);
            }
        }
    }
}

// ===========================================================================
// Operand preparation
// ===========================================================================
__global__ void split_arr(const float* __restrict__ in,
                          __nv_bfloat16* __restrict__ hi, __nv_bfloat16* __restrict__ lo,
                          long n)
{
    long i = ((long)blockIdx.x * 256 + threadIdx.x) * 2;
    if (i >= n) return;
    float2 v = *(const float2*)(in + i);
    uint32_t hp, lp;
    split2(v.x, v.y, hp, lp);
    *(uint32_t*)(hi + i) = hp;
    *(uint32_t*)(lo + i) = lp;
}

__device__ __forceinline__ void decode_kg(int kg, int& K, int& k)
{
    if (kg < 3)      { K = 3; k = kg; }
    else if (kg < 7) { K = 4; k = kg - 3; }
    else             { K = 5; k = kg - 7; }
}

__global__ void pack_wg(const float* __restrict__ c1w3, const float* __restrict__ c1w4,
                        const float* __restrict__ c1w5, const float* __restrict__ c2w3,
                        const float* __restrict__ c2w4, const float* __restrict__ c2w5)
{
    long idx = (long)blockIdx.x * 256 + threadIdx.x;
    if (idx >= (long)NG_PAD * Hh) return;
    int ch = idx / Hh, h = idx % Hh;
    float v = 0.f;
    if (ch < 2400) {
        int kg = ch / 200, r = ch % 200;
        int conv = r / 100, cco = r % 100;
        int K, k; decode_kg(kg, K, k);
        const float* w;
        if (conv == 0) w = (K == 3) ? c1w3 : (K == 4) ? c1w4 : c1w5;
        else           w = (K == 3) ? c2w3 : (K == 4) ? c2w4 : c2w5;
        v = w[(long)cco * Hh * K + h * K + k];
    }
    __nv_bfloat16 hb = __float2bfloat16(v);
    g_Wgh[idx] = hb;
    g_Wgl[idx] = __float2bfloat16(v - __bfloat162float(hb));
}

__global__ void pack_wa(const float* __restrict__ c3w3, const float* __restrict__ c3w4,
                        const float* __restrict__ c3w5)
{
    long idx = (long)blockIdx.x * 256 + threadIdx.x;
    if (idx >= (long)NA_PAD * Hh) return;
    int ch = idx / Hh, h = idx % Hh;
    float v = 0.f;
    if (ch < 1200) {
        int kg = ch / 100, cco = ch % 100;
        int K, k; decode_kg(kg, K, k);
        const float* w = (K == 3) ? c3w3 : (K == 4) ? c3w4 : c3w5;
        v = w[(long)cco * Hh * K + h * K + k];
    }
    __nv_bfloat16 hb = __float2bfloat16(v);
    g_Wah[idx] = hb;
    g_Wal[idx] = __float2bfloat16(v - __bfloat162float(hb));
}

// ===========================================================================
// squash: fp32 h2 -> bf16 hi/lo squashed capsules
// ===========================================================================
__global__ void squash_kernel()
{
    int idx = blockIdx.x * 256 + threadIdx.x;
    if (idx >= MSZ) return;
    float v[6];
    v[0] = g_h2[(long)5 * MSZ + idx];
    #pragma unroll
    for (int j = 1; j < 6; j++) v[j] = g_h2[(long)(j - 1) * MSZ + idx];
    float sq = 1e-16f;
    #pragma unroll
    for (int j = 0; j < 6; j++) sq += v[j] * v[j];
    float sc = sqrtf(sq) / (1.f + sq);
    #pragma unroll
    for (int j = 0; j < 6; j++) {
        float s = v[j] * sc;
        __nv_bfloat16 hb = __float2bfloat16(s);
        g_sqh[(long)j * MSZ + idx] = hb;
        g_sql[(long)j * MSZ + idx] = __float2bfloat16(s - __bfloat162float(hb));
    }
}

// ===========================================================================
// Conv epilogues / fca / priors / routing / final
// ===========================================================================
__global__ void aspect_epi(const float* __restrict__ b3, const float* __restrict__ b4,
                           const float* __restrict__ b5)
{
    int b = blockIdx.x, t = threadIdx.x;
    if (t >= 300) return;
    int g = t / 100, co = t % 100;
    int K = 3 + g;
    int base = (g == 0) ? 0 : (g == 1) ? 3 : 7;
    int pad = K - 2;
    const float* bias = (g == 0) ? b3 : (g == 1) ? b4 : b5;
    float bb = bias[co];
    int Lout = 125 + K;
    float best = 0.f;
    for (int l = 0; l < Lout; l++) {
        float s = bb;
        for (int k = 0; k < K; k++) {
            int ss = l + k - pad;
            if (ss >= 0 && ss < Ss)
                s += g_Ya[((long)b * Ss + ss) * NA_PAD + (base + k) * 100 + co];
        }
        best = fmaxf(best, s);
    }
    g_aspf[b * 300 + t] = best;
}

__global__ void fca_kernel(const float* __restrict__ fw, const float* __restrict__ fb)
{
    __shared__ float af[300];
    int b = blockIdx.x, tid = threadIdx.x;
    for (int i = tid; i < 300; i += 128) af[i] = g_aspf[b * 300 + i];
    __syncthreads();
    if (tid < COn) {
        float s = fb[tid];
        for (int c = 0; c < 300; c++) s += af[c] * fw[tid * 300 + c];
        g_asp[b * COn + tid] = s;
    }
}

__global__ void gated_epi(const float* __restrict__ b13, const float* __restrict__ b14,
                          const float* __restrict__ b15, const float* __restrict__ b23,
                          const float* __restrict__ b24, const float* __restrict__ b25)
{
    int i = blockIdx.x, t = threadIdx.x;
    if (t >= 300) return;
    int b = i & 63;
    int g = t / 100, co = t % 100;
    int K = 3 + g;
    int base = (g == 0) ? 0 : (g == 1) ? 3 : 7;
    const float* bias1 = (g == 0) ? b13 : (g == 1) ? b14 : b15;
    const float* bias2 = (g == 0) ? b23 : (g == 1) ? b24 : b25;
    float c1b = bias1[co];
    float c2b = bias2[co] + g_asp[b * COn + co];
    int Lout = Ss - K + 1;
    float best = -1e30f;
    for (int l = 0; l < Lout; l++) {
        float s1 = c1b, s2 = c2b;
        for (int k = 0; k < K; k++) {
            long row = (long)i * Ss + l + k;
            s1 += g_Yg[row * NG_PAD + (base + k) * 200 + co];
            s2 += g_Yg[row * NG_PAD + (base + k) * 200 + 100 + co];
        }
        float val = tanhf(s1) * fmaxf(s2, 0.f);
        best = fmaxf(best, val);
    }
    g_z[i * 300 + t] = best;
}

__global__ void priors_kernel(const float* __restrict__ rw)
{
    __shared__ float cap[1800];
    int b = blockIdx.x, n = blockIdx.y, tid = threadIdx.x;
    for (int idx = tid; idx < 1800; idx += 72) {
        int i = idx / 300, c = idx % 300;
        cap[idx] = (i == 0) ? g_aspf[b * 300 + c] : g_z[((i - 1) * Bb + b) * 300 + c];
    }
    __syncthreads();
    int i = tid / 12, s = tid % 12;
    float acc = 0.f;
    const float* rp = rw + ((long)(n * 6 + i) * 300) * 12 + s;
    const float* cp = &cap[i * 300];
    for (int c = 0; c < 300; c++) acc += cp[c] * rp[c * 12];
    g_priors[((n * Bb + b) * 6 + i) * 12 + s] = acc;
}

__global__ void routing_kernel()
{
    int gid = blockIdx.x * blockDim.x + threadIdx.x;
    if (gid >= Nn * Bb) return;
    float pr[72];
    #pragma unroll
    for (int j = 0; j < 72; j++) pr[j] = g_priors[gid * 72 + j];

    float logits[6] = {0, 0, 0, 0, 0, 0};
    float vote[12];
    #pragma unroll
    for (int it = 0; it < 3; it++) {
        float mx = logits[0];
        #pragma unroll
        for (int i = 1; i < 6; i++) mx = fmaxf(mx, logits[i]);
        float e[6], se = 0.f;
        #pragma unroll
        for (int i = 0; i < 6; i++) { e[i] = expf(logits[i] - mx); se += e[i]; }
        float inv = 1.f / se;
        #pragma unroll
        for (int s = 0; s < 12; s++) {
            float v = 0.f;
            #pragma unroll
            for (int i = 0; i < 6; i++) v += e[i] * pr[i * 12 + s];
            vote[s] = v * inv;
        }
        if (it < 2) {
            float sq = 1e-16f;
            #pragma unroll
            for (int s = 0; s < 12; s++) sq += vote[s] * vote[s];
            float sc = sqrtf(sq) / (1.f + sq);
            #pragma unroll
            for (int i = 0; i < 6; i++) {
                float d = 0.f;
                #pragma unroll
                for (int s = 0; s < 12; s++) d += pr[i * 12 + s] * vote[s];
                logits[i] += d * sc;
            }
        }
    }
    #pragma unroll
    for (int s = 0; s < 12; s++) g_vote[gid * 12 + s] = vote[s];
}

__global__ void final_kernel(const float* __restrict__ x, float* __restrict__ out)
{
    int idx = blockIdx.x * 256 + threadIdx.x;
    if (idx >= MSZ) return;
    int b = idx / (Ss * Hh);
    int h = idx % Hh;
    out[idx] = x[idx] + g_h2[(long)5 * MSZ + idx] + g_vote[b * Hh + h];
}

// ===========================================================================
extern "C" void kernel_launch(void* const* d_in, const int* in_sizes, int n_in,
                              void* d_out, int out_size)
{
    const float* x     = (const float*)d_in[0];
    const float* fc1_w = (const float*)d_in[1];
    const float* fc1_b = (const float*)d_in[2];
    const float* fc2_w = (const float*)d_in[3];
    const float* fc2_b = (const float*)d_in[4];
    const float* c1_w3 = (const float*)d_in[5];
    const float* c1_b3 = (const float*)d_in[6];
    const float* c1_w4 = (const float*)d_in[7];
    const float* c1_b4 = (const float*)d_in[8];
    const float* c1_w5 = (const float*)d_in[9];
    const float* c1_b5 = (const float*)d_in[10];
    const float* c2_w3 = (const float*)d_in[11];
    const float* c2_b3 = (const float*)d_in[12];
    const float* c2_w4 = (const float*)d_in[13];
    const float* c2_b4 = (const float*)d_in[14];
    const float* c2_w5 = (const float*)d_in[15];
    const float* c2_b5 = (const float*)d_in[16];
    const float* c3_w3 = (const float*)d_in[17];
    const float* c3_b3 = (const float*)d_in[18];
    const float* c3_w4 = (const float*)d_in[19];
    const float* c3_b4 = (const float*)d_in[20];
    const float* c3_w5 = (const float*)d_in[21];
    const float* c3_b5 = (const float*)d_in[22];
    const float* fca_w = (const float*)d_in[23];
    const float* fca_b = (const float*)d_in[24];
    const float* rw    = (const float*)d_in[25];
    float* out = (float*)d_out;

    __nv_bfloat16 *p_xh, *p_xl, *p_f1h, *p_f1l, *p_f2h, *p_f2l;
    __nv_bfloat16 *p_h1h, *p_h1l, *p_sqh, *p_sql, *p_Wgh, *p_Wgl, *p_Wah, *p_Wal;
    float *p_h2, *p_Yg, *p_Ya;
    cudaGetSymbolAddress((void**)&p_xh,  g_xh);
    cudaGetSymbolAddress((void**)&p_xl,  g_xl);
    cudaGetSymbolAddress((void**)&p_f1h, g_f1h);
    cudaGetSymbolAddress((void**)&p_f1l, g_f1l);
    cudaGetSymbolAddress((void**)&p_f2h, g_f2h);
    cudaGetSymbolAddress((void**)&p_f2l, g_f2l);
    cudaGetSymbolAddress((void**)&p_h1h, g_h1h);
    cudaGetSymbolAddress((void**)&p_h1l, g_h1l);
    cudaGetSymbolAddress((void**)&p_sqh, g_sqh);
    cudaGetSymbolAddress((void**)&p_sql, g_sql);
    cudaGetSymbolAddress((void**)&p_Wgh, g_Wgh);
    cudaGetSymbolAddress((void**)&p_Wgl, g_Wgl);
    cudaGetSymbolAddress((void**)&p_Wah, g_Wah);
    cudaGetSymbolAddress((void**)&p_Wal, g_Wal);
    cudaGetSymbolAddress((void**)&p_h2,  g_h2);
    cudaGetSymbolAddress((void**)&p_Yg,  g_Yg);
    cudaGetSymbolAddress((void**)&p_Ya,  g_Ya);

    cudaFuncSetAttribute(mma_gemm<0>, cudaFuncAttributeMaxDynamicSharedMemorySize, SMEM_REQ);
    cudaFuncSetAttribute(mma_gemm<1>, cudaFuncAttributeMaxDynamicSharedMemorySize, SMEM_REQ);
    cudaFuncSetAttribute(mma_gemm<2>, cudaFuncAttributeMaxDynamicSharedMemorySize, SMEM_REQ);

    // 0) operand prep
    split_arr<<<(MSZ / 2 + 255) / 256, 256>>>(x, p_xh, p_xl, MSZ);
    split_arr<<<((long)T1K * Aa * Hh / 2 + 255) / 256, 256>>>(fc1_w, p_f1h, p_f1l, (long)T1K * Aa * Hh);
    split_arr<<<((long)T1K * Hh * Aa / 2 + 255) / 256, 256>>>(fc2_w, p_f2h, p_f2l, (long)T1K * Hh * Aa);
    pack_wg<<<((long)NG_PAD * Hh + 255) / 256, 256>>>(c1_w3, c1_w4, c1_w5, c2_w3, c2_w4, c2_w5);
    pack_wa<<<((long)NA_PAD * Hh + 255) / 256, 256>>>(c3_w3, c3_w4, c3_w5);

    // 1) h1 = relu(x @ fc1_w^T + b)  -> bf16 hi/lo
    mma_gemm<2><<<dim3(Aa / 128, M1 / 128, T1K), 256, SMEM_REQ>>>(
        p_xh, p_xl, p_f1h, p_f1l, fc1_b, nullptr, p_h1h, p_h1l,
        Aa, Hh, 0L, (long)Aa * Hh, (long)Aa, (long)M1 * Aa);

    // 2) h2 = relu(h1 @ fc2_w^T + b) -> fp32
    mma_gemm<1><<<dim3(Hh / 128, M1 / 128, T1K), 256, SMEM_REQ>>>(
        p_h1h, p_h1l, p_f2h, p_f2l, fc2_b, p_h2, nullptr, nullptr,
        Hh, Aa, (long)M1 * Aa, (long)Hh * Aa, (long)Hh, (long)M1 * Hh);

    // 3) squash -> bf16 hi/lo capsules
    squash_kernel<<<(MSZ + 255) / 256, 256>>>();

    // 4) conv GEMMs
    mma_gemm<0><<<dim3(NA_PAD / 128, M1 / 128, 1), 256, SMEM_REQ>>>(
        p_sqh, p_sql, p_Wah, p_Wal, nullptr, p_Ya, nullptr, nullptr,
        NA_PAD, Hh, 0L, 0L, 0L, 0L);
    mma_gemm<0><<<dim3(NG_PAD / 128, MG / 128, 1), 256, SMEM_REQ>>>(
        p_sqh + (long)MSZ, p_sql + (long)MSZ, p_Wgh, p_Wgl, nullptr, p_Yg, nullptr, nullptr,
        NG_PAD, Hh, 0L, 0L, 0L, 0L);

    // 5) epilogues
    aspect_epi<<<Bb, 320>>>(c3_b3, c3_b4, c3_b5);
    fca_kernel<<<Bb, 128>>>(fca_w, fca_b);
    gated_epi<<<TnK * Bb, 320>>>(c1_b3, c1_b4, c1_b5, c2_b3, c2_b4, c2_b5);

    // 6) priors + routing
    priors_kernel<<<dim3(Bb, Nn), 72>>>(rw);
    routing_kernel<<<16, 256>>>();

    // 7) residual add
    final_kernel<<<(MSZ + 255) / 256, 256>>>(x, out);
}

// round 7
// speedup vs baseline: 1.2142x; 1.2142x over previous
#include <cuda_runtime.h>
#include <cuda_bf16.h>
#include <cuda_fp16.h>
#include <math.h>
#include <stdint.h>

// Problem constants
#define Bb   64
#define Ss   128
#define Hh   768
#define Aa   512
#define COn  100
#define TnK  5
#define T1K  6
#define Nn   64
#define SCn  12
#define MSZ  (Bb*Ss*Hh)      // 6291456
#define M1   (Bb*Ss)         // 8192

#define NG_PAD 2432
#define NA_PAD 1280
#define MG     (TnK*M1)      // 40960

// ---------------------------------------------------------------------------
// Scratch (static device globals — allocation-free)
// ---------------------------------------------------------------------------
__device__ __nv_bfloat16 g_xh[MSZ],  g_xl[MSZ];
__device__ __nv_bfloat16 g_f1h[T1K * Aa * Hh], g_f1l[T1K * Aa * Hh];
__device__ __nv_bfloat16 g_f2h[T1K * Hh * Aa], g_f2l[T1K * Hh * Aa];
__device__ __nv_bfloat16 g_h1h[T1K * M1 * Aa], g_h1l[T1K * M1 * Aa];
__device__ float         g_h2[T1K * MSZ];
__device__ __half        g_sqf[T1K * MSZ];                 // fp16 squashed capsules
__device__ __half        g_Wgh[NG_PAD * Hh], g_Wgl[NG_PAD * Hh];
__device__ __half        g_Wah[NA_PAD * Hh], g_Wal[NA_PAD * Hh];
__device__ float g_Yg[(long)MG * NG_PAD];
__device__ float g_Ya[(long)M1 * NA_PAD];
__device__ float g_aspf[Bb * 3 * COn];
__device__ float g_asp[Bb * COn];
__device__ float g_z[TnK * Bb * 3 * COn];
__device__ float g_priors[Nn * Bb * T1K * SCn];
__device__ float g_vote[Nn * Bb * SCn];

// ---------------------------------------------------------------------------
// helpers
// ---------------------------------------------------------------------------
__device__ __forceinline__ void mma_bf16(float* c, const uint32_t* a, const uint32_t* b)
{
    asm volatile(
        "mma.sync.aligned.m16n8k16.row.col.f32.bf16.bf16.f32 "
        "{%0,%1,%2,%3}, {%4,%5,%6,%7}, {%8,%9}, {%0,%1,%2,%3};"
        : "+f"(c[0]), "+f"(c[1]), "+f"(c[2]), "+f"(c[3])
        : "r"(a[0]), "r"(a[1]), "r"(a[2]), "r"(a[3]), "r"(b[0]), "r"(b[1]));
}

__device__ __forceinline__ void mma_fp16(float* c, const uint32_t* a, const uint32_t* b)
{
    asm volatile(
        "mma.sync.aligned.m16n8k16.row.col.f32.f16.f16.f32 "
        "{%0,%1,%2,%3}, {%4,%5,%6,%7}, {%8,%9}, {%0,%1,%2,%3};"
        : "+f"(c[0]), "+f"(c[1]), "+f"(c[2]), "+f"(c[3])
        : "r"(a[0]), "r"(a[1]), "r"(a[2]), "r"(a[3]), "r"(b[0]), "r"(b[1]));
}

__device__ __forceinline__ void split2(float x0, float x1, uint32_t& hp, uint32_t& lp)
{
    asm("cvt.rn.bf16x2.f32 %0, %1, %2;" : "=r"(hp) : "f"(x1), "f"(x0));
    float h0 = __uint_as_float(hp << 16);
    float h1 = __uint_as_float(hp & 0xffff0000u);
    float r0 = x0 - h0, r1 = x1 - h1;
    asm("cvt.rn.bf16x2.f32 %0, %1, %2;" : "=r"(lp) : "f"(r1), "f"(r0));
}

__device__ __forceinline__ void cp16(void* sdst, const void* gsrc)
{
    uint32_t s = (uint32_t)__cvta_generic_to_shared(sdst);
    asm volatile("cp.async.cg.shared.global [%0], [%1], 16;" :: "r"(s), "l"(gsrc));
}
#define CP_COMMIT() asm volatile("cp.async.commit_group;" ::: "memory")
#define CP_WAIT0()  asm volatile("cp.async.wait_group 0;" ::: "memory")

// ===========================================================================
// bf16 3-term split GEMM (fc1 / fc2). OUT: 1 = fp32 bias+relu,
// 2 = bf16 hi/lo bias+relu.
// ===========================================================================
#define KC       32
#define RSTR     40
#define MAT_ELE  (128 * RSTR)           // 5120
#define STG_ELE  (4 * MAT_ELE)
#define SMEM_BF  (2 * STG_ELE * 2)      // 81920 bytes

template<int OUT>
__global__ void __launch_bounds__(256, 2)
mma_gemm_bf(const __nv_bfloat16* __restrict__ Ah, const __nv_bfloat16* __restrict__ Al,
            const __nv_bfloat16* __restrict__ Bh, const __nv_bfloat16* __restrict__ Bl,
            const float* __restrict__ bias,
            float* __restrict__ Cf, __nv_bfloat16* __restrict__ Chi, __nv_bfloat16* __restrict__ Clo,
            int N, int Kd, long sA, long sW, long sB, long sC)
{
    extern __shared__ __nv_bfloat16 sm[];
    long zo = blockIdx.z * sA;
    Ah += zo; Al += zo;
    zo = blockIdx.z * sW;
    Bh += zo; Bl += zo;
    bias += blockIdx.z * sB;
    long co = blockIdx.z * sC;

    int m0 = blockIdx.y * 128, n0 = blockIdx.x * 128;
    int tid = threadIdx.x, lane = tid & 31, wid = tid >> 5;
    int wm = wid >> 2, wn = wid & 3;
    int gid = lane >> 2, tig = lane & 3;

    int crow = tid >> 2, cch = (tid & 3) * 8;

    auto issue = [&](int c, int st) {
        __nv_bfloat16* base = sm + st * STG_ELE;
        int k0 = c * KC;
        #pragma unroll
        for (int r = 0; r < 2; r++) {
            int row = crow + r * 64;
            long ga = (long)(m0 + row) * Kd + k0 + cch;
            long gb = (long)(n0 + row) * Kd + k0 + cch;
            int so = row * RSTR + cch;
            cp16(base + so,               Ah + ga);
            cp16(base + MAT_ELE + so,     Al + ga);
            cp16(base + 2 * MAT_ELE + so, Bh + gb);
            cp16(base + 3 * MAT_ELE + so, Bl + gb);
        }
        CP_COMMIT();
    };

    float acc[4][4][4] = {};
    int nch = Kd / KC;

    issue(0, 0);

    for (int c = 0; c < nch; c++) {
        CP_WAIT0();
        __syncthreads();
        if (c + 1 < nch) issue(c + 1, (c + 1) & 1);

        const __nv_bfloat16* Ahs = sm + (c & 1) * STG_ELE;
        const __nv_bfloat16* Als = Ahs + MAT_ELE;
        const __nv_bfloat16* Bhs = Als + MAT_ELE;
        const __nv_bfloat16* Bls = Bhs + MAT_ELE;

        #pragma unroll
        for (int kk = 0; kk < KC; kk += 16) {
            uint32_t bh[4][2], bl[4][2];
            #pragma unroll
            for (int nt = 0; nt < 4; nt++) {
                int off = (wn * 32 + nt * 8 + gid) * RSTR + kk + tig * 2;
                bh[nt][0] = *(const uint32_t*)(Bhs + off);
                bh[nt][1] = *(const uint32_t*)(Bhs + off + 8);
                bl[nt][0] = *(const uint32_t*)(Bls + off);
                bl[nt][1] = *(const uint32_t*)(Bls + off + 8);
            }
            #pragma unroll
            for (int mt = 0; mt < 4; mt++) {
                int off = (wm * 64 + mt * 16 + gid) * RSTR + kk + tig * 2;
                uint32_t ah[4], al[4];
                ah[0] = *(const uint32_t*)(Ahs + off);
                ah[1] = *(const uint32_t*)(Ahs + off + 8 * RSTR);
                ah[2] = *(const uint32_t*)(Ahs + off + 8);
                ah[3] = *(const uint32_t*)(Ahs + off + 8 * RSTR + 8);
                al[0] = *(const uint32_t*)(Als + off);
                al[1] = *(const uint32_t*)(Als + off + 8 * RSTR);
                al[2] = *(const uint32_t*)(Als + off + 8);
                al[3] = *(const uint32_t*)(Als + off + 8 * RSTR + 8);
                #pragma unroll
                for (int nt = 0; nt < 4; nt++) {
                    mma_bf16(acc[mt][nt], ah, bh[nt]);
                    mma_bf16(acc[mt][nt], ah, bl[nt]);
                    mma_bf16(acc[mt][nt], al, bh[nt]);
                }
            }
        }
        __syncthreads();
    }

    #pragma unroll
    for (int mt = 0; mt < 4; mt++) {
        long m = m0 + wm * 64 + mt * 16 + gid;
        #pragma unroll
        for (int nt = 0; nt < 4; nt++) {
            int col = n0 + wn * 32 + nt * 8 + tig * 2;
            float b0 = bias[col], b1 = bias[col + 1];
            float v00 = fmaxf(acc[mt][nt][0] + b0, 0.f);
            float v01 = fmaxf(acc[mt][nt][1] + b1, 0.f);
            float v10 = fmaxf(acc[mt][nt][2] + b0, 0.f);
            float v11 = fmaxf(acc[mt][nt][3] + b1, 0.f);
            if (OUT == 2) {
                uint32_t hp, lp;
                split2(v00, v01, hp, lp);
                *(uint32_t*)(Chi + co + m * N + col) = hp;
                *(uint32_t*)(Clo + co + m * N + col) = lp;
                split2(v10, v11, hp, lp);
                *(uint32_t*)(Chi + co + (m + 8) * N + col) = hp;
                *(uint32_t*)(Clo + co + (m + 8) * N + col) = lp;
            } else {
                *(float2*)(Cf + co + m * N + col)       = make_float2(v00, v01);
                *(float2*)(Cf + co + (m + 8) * N + col) = make_float2(v10, v11);
            }
        }
    }
}

// ===========================================================================
// fp16 2-term GEMM (conv GEMMs): C = A_fp16 @ (Bh + Bl)^T
// A rounded once to fp16; weights split hi/lo. 32 MMAs per kk (vs 48).
// ===========================================================================
#define STG3_ELE (3 * MAT_ELE)
#define SMEM_FP  (2 * STG3_ELE * 2)     // 61440 bytes

__global__ void __launch_bounds__(256, 2)
mma_gemm_fp16(const __half* __restrict__ A,
              const __half* __restrict__ Bh, const __half* __restrict__ Bl,
              float* __restrict__ Cf, int N, int Kd)
{
    extern __shared__ __half smh[];
    int m0 = blockIdx.y * 128, n0 = blockIdx.x * 128;
    int tid = threadIdx.x, lane = tid & 31, wid = tid >> 5;
    int wm = wid >> 2, wn = wid & 3;
    int gid = lane >> 2, tig = lane & 3;

    int crow = tid >> 2, cch = (tid & 3) * 8;

    auto issue = [&](int c, int st) {
        __half* base = smh + st * STG3_ELE;
        int k0 = c * KC;
        #pragma unroll
        for (int r = 0; r < 2; r++) {
            int row = crow + r * 64;
            long ga = (long)(m0 + row) * Kd + k0 + cch;
            long gb = (long)(n0 + row) * Kd + k0 + cch;
            int so = row * RSTR + cch;
            cp16(base + so,               A  + ga);
            cp16(base + MAT_ELE + so,     Bh + gb);
            cp16(base + 2 * MAT_ELE + so, Bl + gb);
        }
        CP_COMMIT();
    };

    float acc[4][4][4] = {};
    int nch = Kd / KC;

    issue(0, 0);

    for (int c = 0; c < nch; c++) {
        CP_WAIT0();
        __syncthreads();
        if (c + 1 < nch) issue(c + 1, (c + 1) & 1);

        const __half* As  = smh + (c & 1) * STG3_ELE;
        const __half* Bhs = As + MAT_ELE;
        const __half* Bls = Bhs + MAT_ELE;

        #pragma unroll
        for (int kk = 0; kk < KC; kk += 16) {
            uint32_t bh[4][2], bl[4][2];
            #pragma unroll
            for (int nt = 0; nt < 4; nt++) {
                int off = (wn * 32 + nt * 8 + gid) * RSTR + kk + tig * 2;
                bh[nt][0] = *(const uint32_t*)(Bhs + off);
                bh[nt][1] = *(const uint32_t*)(Bhs + off + 8);
                bl[nt][0] = *(const uint32_t*)(Bls + off);
                bl[nt][1] = *(const uint32_t*)(Bls + off + 8);
            }
            #pragma unroll
            for (int mt = 0; mt < 4; mt++) {
                int off = (wm * 64 + mt * 16 + gid) * RSTR + kk + tig * 2;
                uint32_t ah[4];
                ah[0] = *(const uint32_t*)(As + off);
                ah[1] = *(const uint32_t*)(As + off + 8 * RSTR);
                ah[2] = *(const uint32_t*)(As + off + 8);
                ah[3] = *(const uint32_t*)(As + off + 8 * RSTR + 8);
                #pragma unroll
                for (int nt = 0; nt < 4; nt++) {
                    mma_fp16(acc[mt][nt], ah, bh[nt]);
                    mma_fp16(acc[mt][nt], ah, bl[nt]);
                }
            }
        }
        __syncthreads();
    }

    #pragma unroll
    for (int mt = 0; mt < 4; mt++) {
        long m = m0 + wm * 64 + mt * 16 + gid;
        #pragma unroll
        for (int nt = 0; nt < 4; nt++) {
            int col = n0 + wn * 32 + nt * 8 + tig * 2;
            *(float2*)(Cf + m * N + col)       = make_float2(acc[mt][nt][0], acc[mt][nt][1]);
            *(float2*)(Cf + (m + 8) * N + col) = make_float2(acc[mt][nt][2], acc[mt][nt][3]);
        }
    }
}

// ===========================================================================
// Operand preparation
// ===========================================================================
__global__ void split_arr(const float* __restrict__ in,
                          __nv_bfloat16* __restrict__ hi, __nv_bfloat16* __restrict__ lo,
                          long n)
{
    long i = ((long)blockIdx.x * 256 + threadIdx.x) * 2;
    if (i >= n) return;
    float2 v = *(const float2*)(in + i);
    uint32_t hp, lp;
    split2(v.x, v.y, hp, lp);
    *(uint32_t*)(hi + i) = hp;
    *(uint32_t*)(lo + i) = lp;
}

__device__ __forceinline__ void decode_kg(int kg, int& K, int& k)
{
    if (kg < 3)      { K = 3; k = kg; }
    else if (kg < 7) { K = 4; k = kg - 3; }
    else             { K = 5; k = kg - 7; }
}

__global__ void pack_wg(const float* __restrict__ c1w3, const float* __restrict__ c1w4,
                        const float* __restrict__ c1w5, const float* __restrict__ c2w3,
                        const float* __restrict__ c2w4, const float* __restrict__ c2w5)
{
    long idx = (long)blockIdx.x * 256 + threadIdx.x;
    if (idx >= (long)NG_PAD * Hh) return;
    int ch = idx / Hh, h = idx % Hh;
    float v = 0.f;
    if (ch < 2400) {
        int kg = ch / 200, r = ch % 200;
        int conv = r / 100, cco = r % 100;
        int K, k; decode_kg(kg, K, k);
        const float* w;
        if (conv == 0) w = (K == 3) ? c1w3 : (K == 4) ? c1w4 : c1w5;
        else           w = (K == 3) ? c2w3 : (K == 4) ? c2w4 : c2w5;
        v = w[(long)cco * Hh * K + h * K + k];
    }
    __half hb = __float2half_rn(v);
    g_Wgh[idx] = hb;
    g_Wgl[idx] = __float2half_rn(v - __half2float(hb));
}

__global__ void pack_wa(const float* __restrict__ c3w3, const float* __restrict__ c3w4,
                        const float* __restrict__ c3w5)
{
    long idx = (long)blockIdx.x * 256 + threadIdx.x;
    if (idx >= (long)NA_PAD * Hh) return;
    int ch = idx / Hh, h = idx % Hh;
    float v = 0.f;
    if (ch < 1200) {
        int kg = ch / 100, cco = ch % 100;
        int K, k; decode_kg(kg, K, k);
        const float* w = (K == 3) ? c3w3 : (K == 4) ? c3w4 : c3w5;
        v = w[(long)cco * Hh * K + h * K + k];
    }
    __half hb = __float2half_rn(v);
    g_Wah[idx] = hb;
    g_Wal[idx] = __float2half_rn(v - __half2float(hb));
}

// ===========================================================================
// squash: fp32 h2 -> fp16 squashed capsules
// ===========================================================================
__global__ void squash_kernel()
{
    int idx = blockIdx.x * 256 + threadIdx.x;
    if (idx >= MSZ) return;
    float v[6];
    v[0] = g_h2[(long)5 * MSZ + idx];
    #pragma unroll
    for (int j = 1; j < 6; j++) v[j] = g_h2[(long)(j - 1) * MSZ + idx];
    float sq = 1e-16f;
    #pragma unroll
    for (int j = 0; j < 6; j++) sq += v[j] * v[j];
    float sc = sqrtf(sq) / (1.f + sq);
    #pragma unroll
    for (int j = 0; j < 6; j++)
        g_sqf[(long)j * MSZ + idx] = __float2half_rn(v[j] * sc);
}

// ===========================================================================
// Conv epilogues / fca / priors / routing / final
// ===========================================================================
__global__ void aspect_epi(const float* __restrict__ b3, const float* __restrict__ b4,
                           const float* __restrict__ b5)
{
    int b = blockIdx.x, t = threadIdx.x;
    if (t >= 300) return;
    int g = t / 100, co = t % 100;
    int K = 3 + g;
    int base = (g == 0) ? 0 : (g == 1) ? 3 : 7;
    int pad = K - 2;
    const float* bias = (g == 0) ? b3 : (g == 1) ? b4 : b5;
    float bb = bias[co];
    int Lout = 125 + K;
    float best = 0.f;
    for (int l = 0; l < Lout; l++) {
        float s = bb;
        for (int k = 0; k < K; k++) {
            int ss = l + k - pad;
            if (ss >= 0 && ss < Ss)
                s += g_Ya[((long)b * Ss + ss) * NA_PAD + (base + k) * 100 + co];
        }
        best = fmaxf(best, s);
    }
    g_aspf[b * 300 + t] = best;
}

__global__ void fca_kernel(const float* __restrict__ fw, const float* __restrict__ fb)
{
    __shared__ float af[300];
    int b = blockIdx.x, tid = threadIdx.x;
    for (int i = tid; i < 300; i += 128) af[i] = g_aspf[b * 300 + i];
    __syncthreads();
    if (tid < COn) {
        float s = fb[tid];
        for (int c = 0; c < 300; c++) s += af[c] * fw[tid * 300 + c];
        g_asp[b * COn + tid] = s;
    }
}

__global__ void gated_epi(const float* __restrict__ b13, const float* __restrict__ b14,
                          const float* __restrict__ b15, const float* __restrict__ b23,
                          const float* __restrict__ b24, const float* __restrict__ b25)
{
    int i = blockIdx.x, t = threadIdx.x;
    if (t >= 300) return;
    int b = i & 63;
    int g = t / 100, co = t % 100;
    int K = 3 + g;
    int base = (g == 0) ? 0 : (g == 1) ? 3 : 7;
    const float* bias1 = (g == 0) ? b13 : (g == 1) ? b14 : b15;
    const float* bias2 = (g == 0) ? b23 : (g == 1) ? b24 : b25;
    float c1b = bias1[co];
    float c2b = bias2[co] + g_asp[b * COn + co];
    int Lout = Ss - K + 1;
    float best = -1e30f;
    for (int l = 0; l < Lout; l++) {
        float s1 = c1b, s2 = c2b;
        for (int k = 0; k < K; k++) {
            long row = (long)i * Ss + l + k;
            s1 += g_Yg[row * NG_PAD + (base + k) * 200 + co];
            s2 += g_Yg[row * NG_PAD + (base + k) * 200 + 100 + co];
        }
        float val = tanhf(s1) * fmaxf(s2, 0.f);
        best = fmaxf(best, val);
    }
    g_z[i * 300 + t] = best;
}

__global__ void priors_kernel(const float* __restrict__ rw)
{
    __shared__ float cap[1800];
    int b = blockIdx.x, n = blockIdx.y, tid = threadIdx.x;
    for (int idx = tid; idx < 1800; idx += 72) {
        int i = idx / 300, c = idx % 300;
        cap[idx] = (i == 0) ? g_aspf[b * 300 + c] : g_z[((i - 1) * Bb + b) * 300 + c];
    }
    __syncthreads();
    int i = tid / 12, s = tid % 12;
    float acc = 0.f;
    const float* rp = rw + ((long)(n * 6 + i) * 300) * 12 + s;
    const float* cp = &cap[i * 300];
    for (int c = 0; c < 300; c++) acc += cp[c] * rp[c * 12];
    g_priors[((n * Bb + b) * 6 + i) * 12 + s] = acc;
}

__global__ void routing_kernel()
{
    int gid = blockIdx.x * blockDim.x + threadIdx.x;
    if (gid >= Nn * Bb) return;
    float pr[72];
    #pragma unroll
    for (int j = 0; j < 72; j++) pr[j] = g_priors[gid * 72 + j];

    float logits[6] = {0, 0, 0, 0, 0, 0};
    float vote[12];
    #pragma unroll
    for (int it = 0; it < 3; it++) {
        float mx = logits[0];
        #pragma unroll
        for (int i = 1; i < 6; i++) mx = fmaxf(mx, logits[i]);
        float e[6], se = 0.f;
        #pragma unroll
        for (int i = 0; i < 6; i++) { e[i] = expf(logits[i] - mx); se += e[i]; }
        float inv = 1.f / se;
        #pragma unroll
        for (int s = 0; s < 12; s++) {
            float v = 0.f;
            #pragma unroll
            for (int i = 0; i < 6; i++) v += e[i] * pr[i * 12 + s];
            vote[s] = v * inv;
        }
        if (it < 2) {
            float sq = 1e-16f;
            #pragma unroll
            for (int s = 0; s < 12; s++) sq += vote[s] * vote[s];
            float sc = sqrtf(sq) / (1.f + sq);
            #pragma unroll
            for (int i = 0; i < 6; i++) {
                float d = 0.f;
                #pragma unroll
                for (int s = 0; s < 12; s++) d += pr[i * 12 + s] * vote[s];
                logits[i] += d * sc;
            }
        }
    }
    #pragma unroll
    for (int s = 0; s < 12; s++) g_vote[gid * 12 + s] = vote[s];
}

__global__ void final_kernel(const float* __restrict__ x, float* __restrict__ out)
{
    int idx = blockIdx.x * 256 + threadIdx.x;
    if (idx >= MSZ) return;
    int b = idx / (Ss * Hh);
    int h = idx % Hh;
    out[idx] = x[idx] + g_h2[(long)5 * MSZ + idx] + g_vote[b * Hh + h];
}

// ===========================================================================
extern "C" void kernel_launch(void* const* d_in, const int* in_sizes, int n_in,
                              void* d_out, int out_size)
{
    const float* x     = (const float*)d_in[0];
    const float* fc1_w = (const float*)d_in[1];
    const float* fc1_b = (const float*)d_in[2];
    const float* fc2_w = (const float*)d_in[3];
    const float* fc2_b = (const float*)d_in[4];
    const float* c1_w3 = (const float*)d_in[5];
    const float* c1_b3 = (const float*)d_in[6];
    const float* c1_w4 = (const float*)d_in[7];
    const float* c1_b4 = (const float*)d_in[8];
    const float* c1_w5 = (const float*)d_in[9];
    const float* c1_b5 = (const float*)d_in[10];
    const float* c2_w3 = (const float*)d_in[11];
    const float* c2_b3 = (const float*)d_in[12];
    const float* c2_w4 = (const float*)d_in[13];
    const float* c2_b4 = (const float*)d_in[14];
    const float* c2_w5 = (const float*)d_in[15];
    const float* c2_b5 = (const float*)d_in[16];
    const float* c3_w3 = (const float*)d_in[17];
    const float* c3_b3 = (const float*)d_in[18];
    const float* c3_w4 = (const float*)d_in[19];
    const float* c3_b4 = (const float*)d_in[20];
    const float* c3_w5 = (const float*)d_in[21];
    const float* c3_b5 = (const float*)d_in[22];
    const float* fca_w = (const float*)d_in[23];
    const float* fca_b = (const float*)d_in[24];
    const float* rw    = (const float*)d_in[25];
    float* out = (float*)d_out;

    __nv_bfloat16 *p_xh, *p_xl, *p_f1h, *p_f1l, *p_f2h, *p_f2l, *p_h1h, *p_h1l;
    __half *p_sqf, *p_Wgh, *p_Wgl, *p_Wah, *p_Wal;
    float *p_h2, *p_Yg, *p_Ya;
    cudaGetSymbolAddress((void**)&p_xh,  g_xh);
    cudaGetSymbolAddress((void**)&p_xl,  g_xl);
    cudaGetSymbolAddress((void**)&p_f1h, g_f1h);
    cudaGetSymbolAddress((void**)&p_f1l, g_f1l);
    cudaGetSymbolAddress((void**)&p_f2h, g_f2h);
    cudaGetSymbolAddress((void**)&p_f2l, g_f2l);
    cudaGetSymbolAddress((void**)&p_h1h, g_h1h);
    cudaGetSymbolAddress((void**)&p_h1l, g_h1l);
    cudaGetSymbolAddress((void**)&p_sqf, g_sqf);
    cudaGetSymbolAddress((void**)&p_Wgh, g_Wgh);
    cudaGetSymbolAddress((void**)&p_Wgl, g_Wgl);
    cudaGetSymbolAddress((void**)&p_Wah, g_Wah);
    cudaGetSymbolAddress((void**)&p_Wal, g_Wal);
    cudaGetSymbolAddress((void**)&p_h2,  g_h2);
    cudaGetSymbolAddress((void**)&p_Yg,  g_Yg);
    cudaGetSymbolAddress((void**)&p_Ya,  g_Ya);

    cudaFuncSetAttribute(mma_gemm_bf<1>, cudaFuncAttributeMaxDynamicSharedMemorySize, SMEM_BF);
    cudaFuncSetAttribute(mma_gemm_bf<2>, cudaFuncAttributeMaxDynamicSharedMemorySize, SMEM_BF);
    cudaFuncSetAttribute(mma_gemm_fp16,  cudaFuncAttributeMaxDynamicSharedMemorySize, SMEM_FP);

    // 0) operand prep
    split_arr<<<(MSZ / 2 + 255) / 256, 256>>>(x, p_xh, p_xl, MSZ);
    split_arr<<<((long)T1K * Aa * Hh / 2 + 255) / 256, 256>>>(fc1_w, p_f1h, p_f1l, (long)T1K * Aa * Hh);
    split_arr<<<((long)T1K * Hh * Aa / 2 + 255) / 256, 256>>>(fc2_w, p_f2h, p_f2l, (long)T1K * Hh * Aa);
    pack_wg<<<((long)NG_PAD * Hh + 255) / 256, 256>>>(c1_w3, c1_w4, c1_w5, c2_w3, c2_w4, c2_w5);
    pack_wa<<<((long)NA_PAD * Hh + 255) / 256, 256>>>(c3_w3, c3_w4, c3_w5);

    // 1) h1 = relu(x @ fc1_w^T + b)  -> bf16 hi/lo
    mma_gemm_bf<2><<<dim3(Aa / 128, M1 / 128, T1K), 256, SMEM_BF>>>(
        p_xh, p_xl, p_f1h, p_f1l, fc1_b, nullptr, p_h1h, p_h1l,
        Aa, Hh, 0L, (long)Aa * Hh, (long)Aa, (long)M1 * Aa);

    // 2) h2 = relu(h1 @ fc2_w^T + b) -> fp32
    mma_gemm_bf<1><<<dim3(Hh / 128, M1 / 128, T1K), 256, SMEM_BF>>>(
        p_h1h, p_h1l, p_f2h, p_f2l, fc2_b, p_h2, nullptr, nullptr,
        Hh, Aa, (long)M1 * Aa, (long)Hh * Aa, (long)Hh, (long)M1 * Hh);

    // 3) squash -> fp16 capsules
    squash_kernel<<<(MSZ + 255) / 256, 256>>>();

    // 4) conv GEMMs (fp16 2-term)
    mma_gemm_fp16<<<dim3(NA_PAD / 128, M1 / 128, 1), 256, SMEM_FP>>>(
        p_sqf, p_Wah, p_Wal, p_Ya, NA_PAD, Hh);
    mma_gemm_fp16<<<dim3(NG_PAD / 128, MG / 128, 1), 256, SMEM_FP>>>(
        p_sqf + (long)MSZ, p_Wgh, p_Wgl, p_Yg, NG_PAD, Hh);

    // 5) epilogues
    aspect_epi<<<Bb, 320>>>(c3_b3, c3_b4, c3_b5);
    fca_kernel<<<Bb, 128>>>(fca_w, fca_b);
    gated_epi<<<TnK * Bb, 320>>>(c1_b3, c1_b4, c1_b5, c2_b3, c2_b4, c2_b5);

    // 6) priors + routing
    priors_kernel<<<dim3(Bb, Nn), 72>>>(rw);
    routing_kernel<<<16, 256>>>();

    // 7) residual add
    final_kernel<<<(MSZ + 255) / 256, 256>>>(x, out);
}

// round 8
// speedup vs baseline: 1.6930x; 1.3943x over previous
#include <cuda_runtime.h>
#include <cuda_fp16.h>
#include <math.h>
#include <stdint.h>

// Problem constants
#define Bb   64
#define Ss   128
#define Hh   768
#define Aa   512
#define COn  100
#define TnK  5
#define T1K  6
#define Nn   64
#define SCn  12
#define MSZ  (Bb*Ss*Hh)      // 6291456
#define M1   (Bb*Ss)         // 8192

#define NG_PAD 2432
#define NA_PAD 1280
#define MG     (TnK*M1)      // 40960

// ---------------------------------------------------------------------------
// Scratch (static device globals — allocation-free)
// ---------------------------------------------------------------------------
__device__ __half g_xf[MSZ];                               // fp16 x
__device__ __half g_f1h[T1K * Aa * Hh], g_f1l[T1K * Aa * Hh];
__device__ __half g_f2h[T1K * Hh * Aa], g_f2l[T1K * Hh * Aa];
__device__ __half g_h1f[T1K * M1 * Aa];                    // fp16 h1
__device__ float  g_h2[T1K * MSZ];
__device__ __half g_sqf[T1K * MSZ];                        // fp16 squashed capsules
__device__ __half g_Wgh[NG_PAD * Hh];
__device__ __half g_Wah[NA_PAD * Hh];
__device__ __half g_Ygh[(long)MG * NG_PAD];                // fp16 conv GEMM out
__device__ __half g_Yah[(long)M1 * NA_PAD];
__device__ float g_aspf[Bb * 3 * COn];
__device__ float g_asp[Bb * COn];
__device__ float g_z[TnK * Bb * 3 * COn];
__device__ float g_priors[Nn * Bb * T1K * SCn];
__device__ float g_vote[Nn * Bb * SCn];

// ---------------------------------------------------------------------------
// helpers
// ---------------------------------------------------------------------------
__device__ __forceinline__ void mma_fp16(float* c, const uint32_t* a, const uint32_t* b)
{
    asm volatile(
        "mma.sync.aligned.m16n8k16.row.col.f32.f16.f16.f32 "
        "{%0,%1,%2,%3}, {%4,%5,%6,%7}, {%8,%9}, {%0,%1,%2,%3};"
        : "+f"(c[0]), "+f"(c[1]), "+f"(c[2]), "+f"(c[3])
        : "r"(a[0]), "r"(a[1]), "r"(a[2]), "r"(a[3]), "r"(b[0]), "r"(b[1]));
}

__device__ __forceinline__ void cp16(void* sdst, const void* gsrc)
{
    uint32_t s = (uint32_t)__cvta_generic_to_shared(sdst);
    asm volatile("cp.async.cg.shared.global [%0], [%1], 16;" :: "r"(s), "l"(gsrc));
}
#define CP_COMMIT() asm volatile("cp.async.commit_group;" ::: "memory")
#define CP_WAIT0()  asm volatile("cp.async.wait_group 0;" ::: "memory")

#define KC       32
#define RSTR     40
#define MAT_ELE  (128 * RSTR)           // 5120 halfs
#define STG3_ELE (3 * MAT_ELE)
#define STG2_ELE (2 * MAT_ELE)
#define SMEM_FC  (2 * STG3_ELE * 2)     // 61440 bytes
#define SMEM_CV  (2 * STG2_ELE * 2)     // 40960 bytes

// ===========================================================================
// fc GEMM: A fp16 single, W split hi/lo fp16 (2 MMAs/frag).
// OUT: 1 = fp32 bias+relu (fc2), 3 = fp16 bias+relu (fc1)
// ===========================================================================
template<int OUT>
__global__ void __launch_bounds__(256, 2)
mma_fc(const __half* __restrict__ A,
       const __half* __restrict__ Bh, const __half* __restrict__ Bl,
       const float* __restrict__ bias,
       float* __restrict__ Cf, __half* __restrict__ Ch,
       int N, int Kd, long sA, long sW, long sB, long sC)
{
    extern __shared__ __half smh[];
    A  += blockIdx.z * sA;
    long zo = blockIdx.z * sW;
    Bh += zo; Bl += zo;
    bias += blockIdx.z * sB;
    long co = blockIdx.z * sC;

    int m0 = blockIdx.y * 128, n0 = blockIdx.x * 128;
    int tid = threadIdx.x, lane = tid & 31, wid = tid >> 5;
    int wm = wid >> 2, wn = wid & 3;
    int gid = lane >> 2, tig = lane & 3;
    int crow = tid >> 2, cch = (tid & 3) * 8;

    auto issue = [&](int c, int st) {
        __half* base = smh + st * STG3_ELE;
        int k0 = c * KC;
        #pragma unroll
        for (int r = 0; r < 2; r++) {
            int row = crow + r * 64;
            long ga = (long)(m0 + row) * Kd + k0 + cch;
            long gb = (long)(n0 + row) * Kd + k0 + cch;
            int so = row * RSTR + cch;
            cp16(base + so,               A  + ga);
            cp16(base + MAT_ELE + so,     Bh + gb);
            cp16(base + 2 * MAT_ELE + so, Bl + gb);
        }
        CP_COMMIT();
    };

    float acc[4][4][4] = {};
    int nch = Kd / KC;

    issue(0, 0);

    for (int c = 0; c < nch; c++) {
        CP_WAIT0();
        __syncthreads();
        if (c + 1 < nch) issue(c + 1, (c + 1) & 1);

        const __half* As  = smh + (c & 1) * STG3_ELE;
        const __half* Bhs = As + MAT_ELE;
        const __half* Bls = Bhs + MAT_ELE;

        #pragma unroll
        for (int kk = 0; kk < KC; kk += 16) {
            uint32_t bh[4][2], bl[4][2];
            #pragma unroll
            for (int nt = 0; nt < 4; nt++) {
                int off = (wn * 32 + nt * 8 + gid) * RSTR + kk + tig * 2;
                bh[nt][0] = *(const uint32_t*)(Bhs + off);
                bh[nt][1] = *(const uint32_t*)(Bhs + off + 8);
                bl[nt][0] = *(const uint32_t*)(Bls + off);
                bl[nt][1] = *(const uint32_t*)(Bls + off + 8);
            }
            #pragma unroll
            for (int mt = 0; mt < 4; mt++) {
                int off = (wm * 64 + mt * 16 + gid) * RSTR + kk + tig * 2;
                uint32_t ah[4];
                ah[0] = *(const uint32_t*)(As + off);
                ah[1] = *(const uint32_t*)(As + off + 8 * RSTR);
                ah[2] = *(const uint32_t*)(As + off + 8);
                ah[3] = *(const uint32_t*)(As + off + 8 * RSTR + 8);
                #pragma unroll
                for (int nt = 0; nt < 4; nt++) {
                    mma_fp16(acc[mt][nt], ah, bh[nt]);
                    mma_fp16(acc[mt][nt], ah, bl[nt]);
                }
            }
        }
        __syncthreads();
    }

    #pragma unroll
    for (int mt = 0; mt < 4; mt++) {
        long m = m0 + wm * 64 + mt * 16 + gid;
        #pragma unroll
        for (int nt = 0; nt < 4; nt++) {
            int col = n0 + wn * 32 + nt * 8 + tig * 2;
            float b0 = bias[col], b1 = bias[col + 1];
            float v00 = fmaxf(acc[mt][nt][0] + b0, 0.f);
            float v01 = fmaxf(acc[mt][nt][1] + b1, 0.f);
            float v10 = fmaxf(acc[mt][nt][2] + b0, 0.f);
            float v11 = fmaxf(acc[mt][nt][3] + b1, 0.f);
            if (OUT == 3) {
                __half2 p0 = __floats2half2_rn(v00, v01);
                __half2 p1 = __floats2half2_rn(v10, v11);
                *(__half2*)(Ch + co + m * N + col)       = p0;
                *(__half2*)(Ch + co + (m + 8) * N + col) = p1;
            } else {
                *(float2*)(Cf + co + m * N + col)       = make_float2(v00, v01);
                *(float2*)(Cf + co + (m + 8) * N + col) = make_float2(v10, v11);
            }
        }
    }
}

// ===========================================================================
// conv GEMM: pure fp16, 1 MMA/frag. Output fp16.
// ===========================================================================
__global__ void __launch_bounds__(256, 2)
mma_cv(const __half* __restrict__ A, const __half* __restrict__ B,
       __half* __restrict__ Ch, int N, int Kd)
{
    extern __shared__ __half smh[];
    int m0 = blockIdx.y * 128, n0 = blockIdx.x * 128;
    int tid = threadIdx.x, lane = tid & 31, wid = tid >> 5;
    int wm = wid >> 2, wn = wid & 3;
    int gid = lane >> 2, tig = lane & 3;
    int crow = tid >> 2, cch = (tid & 3) * 8;

    auto issue = [&](int c, int st) {
        __half* base = smh + st * STG2_ELE;
        int k0 = c * KC;
        #pragma unroll
        for (int r = 0; r < 2; r++) {
            int row = crow + r * 64;
            long ga = (long)(m0 + row) * Kd + k0 + cch;
            long gb = (long)(n0 + row) * Kd + k0 + cch;
            int so = row * RSTR + cch;
            cp16(base + so,           A + ga);
            cp16(base + MAT_ELE + so, B + gb);
        }
        CP_COMMIT();
    };

    float acc[4][4][4] = {};
    int nch = Kd / KC;

    issue(0, 0);

    for (int c = 0; c < nch; c++) {
        CP_WAIT0();
        __syncthreads();
        if (c + 1 < nch) issue(c + 1, (c + 1) & 1);

        const __half* As = smh + (c & 1) * STG2_ELE;
        const __half* Bs = As + MAT_ELE;

        #pragma unroll
        for (int kk = 0; kk < KC; kk += 16) {
            uint32_t bf[4][2];
            #pragma unroll
            for (int nt = 0; nt < 4; nt++) {
                int off = (wn * 32 + nt * 8 + gid) * RSTR + kk + tig * 2;
                bf[nt][0] = *(const uint32_t*)(Bs + off);
                bf[nt][1] = *(const uint32_t*)(Bs + off + 8);
            }
            #pragma unroll
            for (int mt = 0; mt < 4; mt++) {
                int off = (wm * 64 + mt * 16 + gid) * RSTR + kk + tig * 2;
                uint32_t ah[4];
                ah[0] = *(const uint32_t*)(As + off);
                ah[1] = *(const uint32_t*)(As + off + 8 * RSTR);
                ah[2] = *(const uint32_t*)(As + off + 8);
                ah[3] = *(const uint32_t*)(As + off + 8 * RSTR + 8);
                #pragma unroll
                for (int nt = 0; nt < 4; nt++)
                    mma_fp16(acc[mt][nt], ah, bf[nt]);
            }
        }
        __syncthreads();
    }

    #pragma unroll
    for (int mt = 0; mt < 4; mt++) {
        long m = m0 + wm * 64 + mt * 16 + gid;
        #pragma unroll
        for (int nt = 0; nt < 4; nt++) {
            int col = n0 + wn * 32 + nt * 8 + tig * 2;
            *(__half2*)(Ch + m * N + col)       = __floats2half2_rn(acc[mt][nt][0], acc[mt][nt][1]);
            *(__half2*)(Ch + (m + 8) * N + col) = __floats2half2_rn(acc[mt][nt][2], acc[mt][nt][3]);
        }
    }
}

// ===========================================================================
// Operand preparation
// ===========================================================================
__global__ void round_half(const float* __restrict__ in, __half* __restrict__ o, long n)
{
    long i = ((long)blockIdx.x * 256 + threadIdx.x) * 2;
    if (i >= n) return;
    float2 v = *(const float2*)(in + i);
    *(__half2*)(o + i) = __floats2half2_rn(v.x, v.y);
}

__global__ void split_half(const float* __restrict__ in,
                           __half* __restrict__ hi, __half* __restrict__ lo, long n)
{
    long i = ((long)blockIdx.x * 256 + threadIdx.x) * 2;
    if (i >= n) return;
    float2 v = *(const float2*)(in + i);
    __half h0 = __float2half_rn(v.x), h1 = __float2half_rn(v.y);
    *(__half2*)(hi + i) = __halves2half2(h0, h1);
    *(__half2*)(lo + i) = __floats2half2_rn(v.x - __half2float(h0), v.y - __half2float(h1));
}

__device__ __forceinline__ void decode_kg(int kg, int& K, int& k)
{
    if (kg < 3)      { K = 3; k = kg; }
    else if (kg < 7) { K = 4; k = kg - 3; }
    else             { K = 5; k = kg - 7; }
}

__global__ void pack_wg(const float* __restrict__ c1w3, const float* __restrict__ c1w4,
                        const float* __restrict__ c1w5, const float* __restrict__ c2w3,
                        const float* __restrict__ c2w4, const float* __restrict__ c2w5)
{
    long idx = (long)blockIdx.x * 256 + threadIdx.x;
    if (idx >= (long)NG_PAD * Hh) return;
    int ch = idx / Hh, h = idx % Hh;
    float v = 0.f;
    if (ch < 2400) {
        int kg = ch / 200, r = ch % 200;
        int conv = r / 100, cco = r % 100;
        int K, k; decode_kg(kg, K, k);
        const float* w;
        if (conv == 0) w = (K == 3) ? c1w3 : (K == 4) ? c1w4 : c1w5;
        else           w = (K == 3) ? c2w3 : (K == 4) ? c2w4 : c2w5;
        v = w[(long)cco * Hh * K + h * K + k];
    }
    g_Wgh[idx] = __float2half_rn(v);
}

__global__ void pack_wa(const float* __restrict__ c3w3, const float* __restrict__ c3w4,
                        const float* __restrict__ c3w5)
{
    long idx = (long)blockIdx.x * 256 + threadIdx.x;
    if (idx >= (long)NA_PAD * Hh) return;
    int ch = idx / Hh, h = idx % Hh;
    float v = 0.f;
    if (ch < 1200) {
        int kg = ch / 100, cco = ch % 100;
        int K, k; decode_kg(kg, K, k);
        const float* w = (K == 3) ? c3w3 : (K == 4) ? c3w4 : c3w5;
        v = w[(long)cco * Hh * K + h * K + k];
    }
    g_Wah[idx] = __float2half_rn(v);
}

// ===========================================================================
// squash: fp32 h2 -> fp16 squashed capsules
// ===========================================================================
__global__ void squash_kernel()
{
    int idx = blockIdx.x * 256 + threadIdx.x;
    if (idx >= MSZ) return;
    float v[6];
    v[0] = g_h2[(long)5 * MSZ + idx];
    #pragma unroll
    for (int j = 1; j < 6; j++) v[j] = g_h2[(long)(j - 1) * MSZ + idx];
    float sq = 1e-16f;
    #pragma unroll
    for (int j = 0; j < 6; j++) sq += v[j] * v[j];
    float sc = sqrtf(sq) / (1.f + sq);
    #pragma unroll
    for (int j = 0; j < 6; j++)
        g_sqf[(long)j * MSZ + idx] = __float2half_rn(v[j] * sc);
}

// ===========================================================================
// Conv epilogues / fca / priors / routing / final
// ===========================================================================
__global__ void aspect_epi(const float* __restrict__ b3, const float* __restrict__ b4,
                           const float* __restrict__ b5)
{
    int b = blockIdx.x, t = threadIdx.x;
    if (t >= 300) return;
    int g = t / 100, co = t % 100;
    int K = 3 + g;
    int base = (g == 0) ? 0 : (g == 1) ? 3 : 7;
    int pad = K - 2;
    const float* bias = (g == 0) ? b3 : (g == 1) ? b4 : b5;
    float bb = bias[co];
    int Lout = 125 + K;
    float best = 0.f;
    for (int l = 0; l < Lout; l++) {
        float s = bb;
        for (int k = 0; k < K; k++) {
            int ss = l + k - pad;
            if (ss >= 0 && ss < Ss)
                s += __half2float(g_Yah[((long)b * Ss + ss) * NA_PAD + (base + k) * 100 + co]);
        }
        best = fmaxf(best, s);
    }
    g_aspf[b * 300 + t] = best;
}

__global__ void fca_kernel(const float* __restrict__ fw, const float* __restrict__ fb)
{
    __shared__ float af[300];
    int b = blockIdx.x, tid = threadIdx.x;
    for (int i = tid; i < 300; i += 128) af[i] = g_aspf[b * 300 + i];
    __syncthreads();
    if (tid < COn) {
        float s = fb[tid];
        for (int c = 0; c < 300; c++) s += af[c] * fw[tid * 300 + c];
        g_asp[b * COn + tid] = s;
    }
}

__global__ void gated_epi(const float* __restrict__ b13, const float* __restrict__ b14,
                          const float* __restrict__ b15, const float* __restrict__ b23,
                          const float* __restrict__ b24, const float* __restrict__ b25)
{
    int i = blockIdx.x, t = threadIdx.x;
    if (t >= 300) return;
    int b = i & 63;
    int g = t / 100, co = t % 100;
    int K = 3 + g;
    int base = (g == 0) ? 0 : (g == 1) ? 3 : 7;
    const float* bias1 = (g == 0) ? b13 : (g == 1) ? b14 : b15;
    const float* bias2 = (g == 0) ? b23 : (g == 1) ? b24 : b25;
    float c1b = bias1[co];
    float c2b = bias2[co] + g_asp[b * COn + co];
    int Lout = Ss - K + 1;
    float best = -1e30f;
    for (int l = 0; l < Lout; l++) {
        float s1 = c1b, s2 = c2b;
        for (int k = 0; k < K; k++) {
            long row = (long)i * Ss + l + k;
            s1 += __half2float(g_Ygh[row * NG_PAD + (base + k) * 200 + co]);
            s2 += __half2float(g_Ygh[row * NG_PAD + (base + k) * 200 + 100 + co]);
        }
        float val = tanhf(s1) * fmaxf(s2, 0.f);
        best = fmaxf(best, val);
    }
    g_z[i * 300 + t] = best;
}

__global__ void priors_kernel(const float* __restrict__ rw)
{
    __shared__ float cap[1800];
    int b = blockIdx.x, n = blockIdx.y, tid = threadIdx.x;
    for (int idx = tid; idx < 1800; idx += 72) {
        int i = idx / 300, c = idx % 300;
        cap[idx] = (i == 0) ? g_aspf[b * 300 + c] : g_z[((i - 1) * Bb + b) * 300 + c];
    }
    __syncthreads();
    int i = tid / 12, s = tid % 12;
    float acc = 0.f;
    const float* rp = rw + ((long)(n * 6 + i) * 300) * 12 + s;
    const float* cp = &cap[i * 300];
    for (int c = 0; c < 300; c++) acc += cp[c] * rp[c * 12];
    g_priors[((n * Bb + b) * 6 + i) * 12 + s] = acc;
}

__global__ void routing_kernel()
{
    int gid = blockIdx.x * blockDim.x + threadIdx.x;
    if (gid >= Nn * Bb) return;
    float pr[72];
    #pragma unroll
    for (int j = 0; j < 72; j++) pr[j] = g_priors[gid * 72 + j];

    float logits[6] = {0, 0, 0, 0, 0, 0};
    float vote[12];
    #pragma unroll
    for (int it = 0; it < 3; it++) {
        float mx = logits[0];
        #pragma unroll
        for (int i = 1; i < 6; i++) mx = fmaxf(mx, logits[i]);
        float e[6], se = 0.f;
        #pragma unroll
        for (int i = 0; i < 6; i++) { e[i] = expf(logits[i] - mx); se += e[i]; }
        float inv = 1.f / se;
        #pragma unroll
        for (int s = 0; s < 12; s++) {
            float v = 0.f;
            #pragma unroll
            for (int i = 0; i < 6; i++) v += e[i] * pr[i * 12 + s];
            vote[s] = v * inv;
        }
        if (it < 2) {
            float sq = 1e-16f;
            #pragma unroll
            for (int s = 0; s < 12; s++) sq += vote[s] * vote[s];
            float sc = sqrtf(sq) / (1.f + sq);
            #pragma unroll
            for (int i = 0; i < 6; i++) {
                float d = 0.f;
                #pragma unroll
                for (int s = 0; s < 12; s++) d += pr[i * 12 + s] * vote[s];
                logits[i] += d * sc;
            }
        }
    }
    #pragma unroll
    for (int s = 0; s < 12; s++) g_vote[gid * 12 + s] = vote[s];
}

__global__ void final_kernel(const float* __restrict__ x, float* __restrict__ out)
{
    int idx = blockIdx.x * 256 + threadIdx.x;
    if (idx >= MSZ) return;
    int b = idx / (Ss * Hh);
    int h = idx % Hh;
    out[idx] = x[idx] + g_h2[(long)5 * MSZ + idx] + g_vote[b * Hh + h];
}

// ===========================================================================
extern "C" void kernel_launch(void* const* d_in, const int* in_sizes, int n_in,
                              void* d_out, int out_size)
{
    const float* x     = (const float*)d_in[0];
    const float* fc1_w = (const float*)d_in[1];
    const float* fc1_b = (const float*)d_in[2];
    const float* fc2_w = (const float*)d_in[3];
    const float* fc2_b = (const float*)d_in[4];
    const float* c1_w3 = (const float*)d_in[5];
    const float* c1_b3 = (const float*)d_in[6];
    const float* c1_w4 = (const float*)d_in[7];
    const float* c1_b4 = (const float*)d_in[8];
    const float* c1_w5 = (const float*)d_in[9];
    const float* c1_b5 = (const float*)d_in[10];
    const float* c2_w3 = (const float*)d_in[11];
    const float* c2_b3 = (const float*)d_in[12];
    const float* c2_w4 = (const float*)d_in[13];
    const float* c2_b4 = (const float*)d_in[14];
    const float* c2_w5 = (const float*)d_in[15];
    const float* c2_b5 = (const float*)d_in[16];
    const float* c3_w3 = (const float*)d_in[17];
    const float* c3_b3 = (const float*)d_in[18];
    const float* c3_w4 = (const float*)d_in[19];
    const float* c3_b4 = (const float*)d_in[20];
    const float* c3_w5 = (const float*)d_in[21];
    const float* c3_b5 = (const float*)d_in[22];
    const float* fca_w = (const float*)d_in[23];
    const float* fca_b = (const float*)d_in[24];
    const float* rw    = (const float*)d_in[25];
    float* out = (float*)d_out;

    __half *p_xf, *p_f1h, *p_f1l, *p_f2h, *p_f2l, *p_h1f, *p_sqf, *p_Wgh, *p_Wah, *p_Ygh, *p_Yah;
    float *p_h2;
    cudaGetSymbolAddress((void**)&p_xf,  g_xf);
    cudaGetSymbolAddress((void**)&p_f1h, g_f1h);
    cudaGetSymbolAddress((void**)&p_f1l, g_f1l);
    cudaGetSymbolAddress((void**)&p_f2h, g_f2h);
    cudaGetSymbolAddress((void**)&p_f2l, g_f2l);
    cudaGetSymbolAddress((void**)&p_h1f, g_h1f);
    cudaGetSymbolAddress((void**)&p_sqf, g_sqf);
    cudaGetSymbolAddress((void**)&p_Wgh, g_Wgh);
    cudaGetSymbolAddress((void**)&p_Wah, g_Wah);
    cudaGetSymbolAddress((void**)&p_Ygh, g_Ygh);
    cudaGetSymbolAddress((void**)&p_Yah, g_Yah);
    cudaGetSymbolAddress((void**)&p_h2,  g_h2);

    cudaFuncSetAttribute(mma_fc<1>, cudaFuncAttributeMaxDynamicSharedMemorySize, SMEM_FC);
    cudaFuncSetAttribute(mma_fc<3>, cudaFuncAttributeMaxDynamicSharedMemorySize, SMEM_FC);
    cudaFuncSetAttribute(mma_cv,    cudaFuncAttributeMaxDynamicSharedMemorySize, SMEM_CV);

    // 0) operand prep
    round_half<<<(MSZ / 2 + 255) / 256, 256>>>(x, p_xf, MSZ);
    split_half<<<((long)T1K * Aa * Hh / 2 + 255) / 256, 256>>>(fc1_w, p_f1h, p_f1l, (long)T1K * Aa * Hh);
    split_half<<<((long)T1K * Hh * Aa / 2 + 255) / 256, 256>>>(fc2_w, p_f2h, p_f2l, (long)T1K * Hh * Aa);
    pack_wg<<<((long)NG_PAD * Hh + 255) / 256, 256>>>(c1_w3, c1_w4, c1_w5, c2_w3, c2_w4, c2_w5);
    pack_wa<<<((long)NA_PAD * Hh + 255) / 256, 256>>>(c3_w3, c3_w4, c3_w5);

    // 1) h1 = relu(x @ fc1_w^T + b)  -> fp16
    mma_fc<3><<<dim3(Aa / 128, M1 / 128, T1K), 256, SMEM_FC>>>(
        p_xf, p_f1h, p_f1l, fc1_b, nullptr, p_h1f,
        Aa, Hh, 0L, (long)Aa * Hh, (long)Aa, (long)M1 * Aa);

    // 2) h2 = relu(h1 @ fc2_w^T + b) -> fp32
    mma_fc<1><<<dim3(Hh / 128, M1 / 128, T1K), 256, SMEM_FC>>>(
        p_h1f, p_f2h, p_f2l, fc2_b, p_h2, nullptr,
        Hh, Aa, (long)M1 * Aa, (long)Hh * Aa, (long)Hh, (long)M1 * Hh);

    // 3) squash -> fp16 capsules
    squash_kernel<<<(MSZ + 255) / 256, 256>>>();

    // 4) conv GEMMs (pure fp16, 1 MMA/frag)
    mma_cv<<<dim3(NA_PAD / 128, M1 / 128, 1), 256, SMEM_CV>>>(
        p_sqf, p_Wah, p_Yah, NA_PAD, Hh);
    mma_cv<<<dim3(NG_PAD / 128, MG / 128, 1), 256, SMEM_CV>>>(
        p_sqf + (long)MSZ, p_Wgh, p_Ygh, NG_PAD, Hh);

    // 5) epilogues
    aspect_epi<<<Bb, 320>>>(c3_b3, c3_b4, c3_b5);
    fca_kernel<<<Bb, 128>>>(fca_w, fca_b);
    gated_epi<<<TnK * Bb, 320>>>(c1_b3, c1_b4, c1_b5, c2_b3, c2_b4, c2_b5);

    // 6) priors + routing
    priors_kernel<<<dim3(Bb, Nn), 72>>>(rw);
    routing_kernel<<<16, 256>>>();

    // 7) residual add
    final_kernel<<<(MSZ + 255) / 256, 256>>>(x, out);
}

// round 9
// speedup vs baseline: 1.9109x; 1.1287x over previous
#include <cuda_runtime.h>
#include <cuda_fp16.h>
#include <math.h>
#include <stdint.h>

// Problem constants
#define Bb   64
#define Ss   128
#define Hh   768
#define Aa   512
#define COn  100
#define TnK  5
#define T1K  6
#define Nn   64
#define SCn  12
#define MSZ  (Bb*Ss*Hh)      // 6291456
#define M1   (Bb*Ss)         // 8192

#define NG_PAD 2432
#define NA_PAD 1280
#define MG     (TnK*M1)      // 40960

// ---------------------------------------------------------------------------
// Scratch (static device globals — allocation-free)
// ---------------------------------------------------------------------------
__device__ __half g_xf[MSZ];                               // fp16 x
__device__ __half g_f1f[T1K * Aa * Hh];                    // fp16 fc1 weights
__device__ __half g_f2f[T1K * Hh * Aa];                    // fp16 fc2 weights
__device__ __half g_h1f[T1K * M1 * Aa];                    // fp16 h1
__device__ __half g_h2f[T1K * MSZ];                        // fp16 h2
__device__ __half g_sqf[T1K * MSZ];                        // fp16 squashed capsules
__device__ __half g_Wgh[NG_PAD * Hh];
__device__ __half g_Wah[NA_PAD * Hh];
__device__ __half g_Ygh[(long)MG * NG_PAD];                // fp16 conv GEMM out
__device__ __half g_Yah[(long)M1 * NA_PAD];
__device__ float g_aspf[Bb * 3 * COn];
__device__ float g_asp[Bb * COn];
__device__ float g_z[TnK * Bb * 3 * COn];
__device__ float g_priors[Nn * Bb * T1K * SCn];
__device__ float g_vote[Nn * Bb * SCn];

// ---------------------------------------------------------------------------
// helpers
// ---------------------------------------------------------------------------
__device__ __forceinline__ void mma_fp16(float* c, const uint32_t* a, const uint32_t* b)
{
    asm volatile(
        "mma.sync.aligned.m16n8k16.row.col.f32.f16.f16.f32 "
        "{%0,%1,%2,%3}, {%4,%5,%6,%7}, {%8,%9}, {%0,%1,%2,%3};"
        : "+f"(c[0]), "+f"(c[1]), "+f"(c[2]), "+f"(c[3])
        : "r"(a[0]), "r"(a[1]), "r"(a[2]), "r"(a[3]), "r"(b[0]), "r"(b[1]));
}

__device__ __forceinline__ void cp16(void* sdst, const void* gsrc)
{
    uint32_t s = (uint32_t)__cvta_generic_to_shared(sdst);
    asm volatile("cp.async.cg.shared.global [%0], [%1], 16;" :: "r"(s), "l"(gsrc));
}
#define CP_COMMIT() asm volatile("cp.async.commit_group;" ::: "memory")
#define CP_WAIT0()  asm volatile("cp.async.wait_group 0;" ::: "memory")

#define KC       32
#define RSTR     40
#define MAT_ELE  (128 * RSTR)           // 5120 halfs
#define STG2_ELE (2 * MAT_ELE)
#define SMEM_CV  (2 * STG2_ELE * 2)     // 40960 bytes

// ===========================================================================
// Unified single-term fp16 GEMM (1 MMA/frag), fp16 output.
// BIASRELU: 1 = +bias then relu (fc), 0 = plain (conv). z-batched via strides.
// ===========================================================================
template<int BIASRELU>
__global__ void __launch_bounds__(256, 2)
mma_h(const __half* __restrict__ A, const __half* __restrict__ B,
      const float* __restrict__ bias, __half* __restrict__ Ch,
      int N, int Kd, long sA, long sW, long sB, long sC)
{
    extern __shared__ __half smh[];
    A += blockIdx.z * sA;
    B += blockIdx.z * sW;
    if (BIASRELU) bias += blockIdx.z * sB;
    long co = blockIdx.z * sC;

    int m0 = blockIdx.y * 128, n0 = blockIdx.x * 128;
    int tid = threadIdx.x, lane = tid & 31, wid = tid >> 5;
    int wm = wid >> 2, wn = wid & 3;
    int gid = lane >> 2, tig = lane & 3;
    int crow = tid >> 2, cch = (tid & 3) * 8;

    auto issue = [&](int c, int st) {
        __half* base = smh + st * STG2_ELE;
        int k0 = c * KC;
        #pragma unroll
        for (int r = 0; r < 2; r++) {
            int row = crow + r * 64;
            long ga = (long)(m0 + row) * Kd + k0 + cch;
            long gb = (long)(n0 + row) * Kd + k0 + cch;
            int so = row * RSTR + cch;
            cp16(base + so,           A + ga);
            cp16(base + MAT_ELE + so, B + gb);
        }
        CP_COMMIT();
    };

    float acc[4][4][4] = {};
    int nch = Kd / KC;

    issue(0, 0);

    for (int c = 0; c < nch; c++) {
        CP_WAIT0();
        __syncthreads();
        if (c + 1 < nch) issue(c + 1, (c + 1) & 1);

        const __half* As = smh + (c & 1) * STG2_ELE;
        const __half* Bs = As + MAT_ELE;

        #pragma unroll
        for (int kk = 0; kk < KC; kk += 16) {
            uint32_t bf[4][2];
            #pragma unroll
            for (int nt = 0; nt < 4; nt++) {
                int off = (wn * 32 + nt * 8 + gid) * RSTR + kk + tig * 2;
                bf[nt][0] = *(const uint32_t*)(Bs + off);
                bf[nt][1] = *(const uint32_t*)(Bs + off + 8);
            }
            #pragma unroll
            for (int mt = 0; mt < 4; mt++) {
                int off = (wm * 64 + mt * 16 + gid) * RSTR + kk + tig * 2;
                uint32_t ah[4];
                ah[0] = *(const uint32_t*)(As + off);
                ah[1] = *(const uint32_t*)(As + off + 8 * RSTR);
                ah[2] = *(const uint32_t*)(As + off + 8);
                ah[3] = *(const uint32_t*)(As + off + 8 * RSTR + 8);
                #pragma unroll
                for (int nt = 0; nt < 4; nt++)
                    mma_fp16(acc[mt][nt], ah, bf[nt]);
            }
        }
        __syncthreads();
    }

    #pragma unroll
    for (int mt = 0; mt < 4; mt++) {
        long m = m0 + wm * 64 + mt * 16 + gid;
        #pragma unroll
        for (int nt = 0; nt < 4; nt++) {
            int col = n0 + wn * 32 + nt * 8 + tig * 2;
            float v00 = acc[mt][nt][0], v01 = acc[mt][nt][1];
            float v10 = acc[mt][nt][2], v11 = acc[mt][nt][3];
            if (BIASRELU) {
                float b0 = bias[col], b1 = bias[col + 1];
                v00 = fmaxf(v00 + b0, 0.f); v01 = fmaxf(v01 + b1, 0.f);
                v10 = fmaxf(v10 + b0, 0.f); v11 = fmaxf(v11 + b1, 0.f);
            }
            *(__half2*)(Ch + co + m * N + col)       = __floats2half2_rn(v00, v01);
            *(__half2*)(Ch + co + (m + 8) * N + col) = __floats2half2_rn(v10, v11);
        }
    }
}

// ===========================================================================
// Operand preparation
// ===========================================================================
__global__ void round_half(const float* __restrict__ in, __half* __restrict__ o, long n)
{
    long i = ((long)blockIdx.x * 256 + threadIdx.x) * 2;
    if (i >= n) return;
    float2 v = *(const float2*)(in + i);
    *(__half2*)(o + i) = __floats2half2_rn(v.x, v.y);
}

__device__ __forceinline__ void decode_kg(int kg, int& K, int& k)
{
    if (kg < 3)      { K = 3; k = kg; }
    else if (kg < 7) { K = 4; k = kg - 3; }
    else             { K = 5; k = kg - 7; }
}

__global__ void pack_wg(const float* __restrict__ c1w3, const float* __restrict__ c1w4,
                        const float* __restrict__ c1w5, const float* __restrict__ c2w3,
                        const float* __restrict__ c2w4, const float* __restrict__ c2w5)
{
    long idx = (long)blockIdx.x * 256 + threadIdx.x;
    if (idx >= (long)NG_PAD * Hh) return;
    int ch = idx / Hh, h = idx % Hh;
    float v = 0.f;
    if (ch < 2400) {
        int kg = ch / 200, r = ch % 200;
        int conv = r / 100, cco = r % 100;
        int K, k; decode_kg(kg, K, k);
        const float* w;
        if (conv == 0) w = (K == 3) ? c1w3 : (K == 4) ? c1w4 : c1w5;
        else           w = (K == 3) ? c2w3 : (K == 4) ? c2w4 : c2w5;
        v = w[(long)cco * Hh * K + h * K + k];
    }
    g_Wgh[idx] = __float2half_rn(v);
}

__global__ void pack_wa(const float* __restrict__ c3w3, const float* __restrict__ c3w4,
                        const float* __restrict__ c3w5)
{
    long idx = (long)blockIdx.x * 256 + threadIdx.x;
    if (idx >= (long)NA_PAD * Hh) return;
    int ch = idx / Hh, h = idx % Hh;
    float v = 0.f;
    if (ch < 1200) {
        int kg = ch / 100, cco = ch % 100;
        int K, k; decode_kg(kg, K, k);
        const float* w = (K == 3) ? c3w3 : (K == 4) ? c3w4 : c3w5;
        v = w[(long)cco * Hh * K + h * K + k];
    }
    g_Wah[idx] = __float2half_rn(v);
}

// ===========================================================================
// squash: fp16 h2 -> fp16 squashed capsules
// ===========================================================================
__global__ void squash_kernel()
{
    int idx = blockIdx.x * 256 + threadIdx.x;
    if (idx >= MSZ) return;
    float v[6];
    v[0] = __half2float(g_h2f[(long)5 * MSZ + idx]);
    #pragma unroll
    for (int j = 1; j < 6; j++) v[j] = __half2float(g_h2f[(long)(j - 1) * MSZ + idx]);
    float sq = 1e-16f;
    #pragma unroll
    for (int j = 0; j < 6; j++) sq += v[j] * v[j];
    float sc = sqrtf(sq) / (1.f + sq);
    #pragma unroll
    for (int j = 0; j < 6; j++)
        g_sqf[(long)j * MSZ + idx] = __float2half_rn(v[j] * sc);
}

// ===========================================================================
// Conv epilogues / fca / priors / routing / final
// ===========================================================================
__global__ void aspect_epi(const float* __restrict__ b3, const float* __restrict__ b4,
                           const float* __restrict__ b5)
{
    int b = blockIdx.x, t = threadIdx.x;
    if (t >= 300) return;
    int g = t / 100, co = t % 100;
    int K = 3 + g;
    int base = (g == 0) ? 0 : (g == 1) ? 3 : 7;
    int pad = K - 2;
    const float* bias = (g == 0) ? b3 : (g == 1) ? b4 : b5;
    float bb = bias[co];
    int Lout = 125 + K;
    float best = 0.f;
    for (int l = 0; l < Lout; l++) {
        float s = bb;
        for (int k = 0; k < K; k++) {
            int ss = l + k - pad;
            if (ss >= 0 && ss < Ss)
                s += __half2float(g_Yah[((long)b * Ss + ss) * NA_PAD + (base + k) * 100 + co]);
        }
        best = fmaxf(best, s);
    }
    g_aspf[b * 300 + t] = best;
}

__global__ void fca_kernel(const float* __restrict__ fw, const float* __restrict__ fb)
{
    __shared__ float af[300];
    int b = blockIdx.x, tid = threadIdx.x;
    for (int i = tid; i < 300; i += 128) af[i] = g_aspf[b * 300 + i];
    __syncthreads();
    if (tid < COn) {
        float s = fb[tid];
        for (int c = 0; c < 300; c++) s += af[c] * fw[tid * 300 + c];
        g_asp[b * COn + tid] = s;
    }
}

__global__ void gated_epi(const float* __restrict__ b13, const float* __restrict__ b14,
                          const float* __restrict__ b15, const float* __restrict__ b23,
                          const float* __restrict__ b24, const float* __restrict__ b25)
{
    int i = blockIdx.x, t = threadIdx.x;
    if (t >= 300) return;
    int b = i & 63;
    int g = t / 100, co = t % 100;
    int K = 3 + g;
    int base = (g == 0) ? 0 : (g == 1) ? 3 : 7;
    const float* bias1 = (g == 0) ? b13 : (g == 1) ? b14 : b15;
    const float* bias2 = (g == 0) ? b23 : (g == 1) ? b24 : b25;
    float c1b = bias1[co];
    float c2b = bias2[co] + g_asp[b * COn + co];
    int Lout = Ss - K + 1;
    float best = -1e30f;
    for (int l = 0; l < Lout; l++) {
        float s1 = c1b, s2 = c2b;
        for (int k = 0; k < K; k++) {
            long row = (long)i * Ss + l + k;
            s1 += __half2float(g_Ygh[row * NG_PAD + (base + k) * 200 + co]);
            s2 += __half2float(g_Ygh[row * NG_PAD + (base + k) * 200 + 100 + co]);
        }
        float val = tanhf(s1) * fmaxf(s2, 0.f);
        best = fmaxf(best, val);
    }
    g_z[i * 300 + t] = best;
}

__global__ void priors_kernel(const float* __restrict__ rw)
{
    __shared__ float cap[1800];
    int b = blockIdx.x, n = blockIdx.y, tid = threadIdx.x;
    for (int idx = tid; idx < 1800; idx += 72) {
        int i = idx / 300, c = idx % 300;
        cap[idx] = (i == 0) ? g_aspf[b * 300 + c] : g_z[((i - 1) * Bb + b) * 300 + c];
    }
    __syncthreads();
    int i = tid / 12, s = tid % 12;
    float acc = 0.f;
    const float* rp = rw + ((long)(n * 6 + i) * 300) * 12 + s;
    const float* cp = &cap[i * 300];
    for (int c = 0; c < 300; c++) acc += cp[c] * rp[c * 12];
    g_priors[((n * Bb + b) * 6 + i) * 12 + s] = acc;
}

__global__ void routing_kernel()
{
    int gid = blockIdx.x * blockDim.x + threadIdx.x;
    if (gid >= Nn * Bb) return;
    float pr[72];
    #pragma unroll
    for (int j = 0; j < 72; j++) pr[j] = g_priors[gid * 72 + j];

    float logits[6] = {0, 0, 0, 0, 0, 0};
    float vote[12];
    #pragma unroll
    for (int it = 0; it < 3; it++) {
        float mx = logits[0];
        #pragma unroll
        for (int i = 1; i < 6; i++) mx = fmaxf(mx, logits[i]);
        float e[6], se = 0.f;
        #pragma unroll
        for (int i = 0; i < 6; i++) { e[i] = expf(logits[i] - mx); se += e[i]; }
        float inv = 1.f / se;
        #pragma unroll
        for (int s = 0; s < 12; s++) {
            float v = 0.f;
            #pragma unroll
            for (int i = 0; i < 6; i++) v += e[i] * pr[i * 12 + s];
            vote[s] = v * inv;
        }
        if (it < 2) {
            float sq = 1e-16f;
            #pragma unroll
            for (int s = 0; s < 12; s++) sq += vote[s] * vote[s];
            float sc = sqrtf(sq) / (1.f + sq);
            #pragma unroll
            for (int i = 0; i < 6; i++) {
                float d = 0.f;
                #pragma unroll
                for (int s = 0; s < 12; s++) d += pr[i * 12 + s] * vote[s];
                logits[i] += d * sc;
            }
        }
    }
    #pragma unroll
    for (int s = 0; s < 12; s++) g_vote[gid * 12 + s] = vote[s];
}

__global__ void final_kernel(const float* __restrict__ x, float* __restrict__ out)
{
    int idx = blockIdx.x * 256 + threadIdx.x;
    if (idx >= MSZ) return;
    int b = idx / (Ss * Hh);
    int h = idx % Hh;
    out[idx] = x[idx] + __half2float(g_h2f[(long)5 * MSZ + idx]) + g_vote[b * Hh + h];
}

// ===========================================================================
extern "C" void kernel_launch(void* const* d_in, const int* in_sizes, int n_in,
                              void* d_out, int out_size)
{
    const float* x     = (const float*)d_in[0];
    const float* fc1_w = (const float*)d_in[1];
    const float* fc1_b = (const float*)d_in[2];
    const float* fc2_w = (const float*)d_in[3];
    const float* fc2_b = (const float*)d_in[4];
    const float* c1_w3 = (const float*)d_in[5];
    const float* c1_b3 = (const float*)d_in[6];
    const float* c1_w4 = (const float*)d_in[7];
    const float* c1_b4 = (const float*)d_in[8];
    const float* c1_w5 = (const float*)d_in[9];
    const float* c1_b5 = (const float*)d_in[10];
    const float* c2_w3 = (const float*)d_in[11];
    const float* c2_b3 = (const float*)d_in[12];
    const float* c2_w4 = (const float*)d_in[13];
    const float* c2_b4 = (const float*)d_in[14];
    const float* c2_w5 = (const float*)d_in[15];
    const float* c2_b5 = (const float*)d_in[16];
    const float* c3_w3 = (const float*)d_in[17];
    const float* c3_b3 = (const float*)d_in[18];
    const float* c3_w4 = (const float*)d_in[19];
    const float* c3_b4 = (const float*)d_in[20];
    const float* c3_w5 = (const float*)d_in[21];
    const float* c3_b5 = (const float*)d_in[22];
    const float* fca_w = (const float*)d_in[23];
    const float* fca_b = (const float*)d_in[24];
    const float* rw    = (const float*)d_in[25];
    float* out = (float*)d_out;

    __half *p_xf, *p_f1f, *p_f2f, *p_h1f, *p_h2f, *p_sqf, *p_Wgh, *p_Wah, *p_Ygh, *p_Yah;
    cudaGetSymbolAddress((void**)&p_xf,  g_xf);
    cudaGetSymbolAddress((void**)&p_f1f, g_f1f);
    cudaGetSymbolAddress((void**)&p_f2f, g_f2f);
    cudaGetSymbolAddress((void**)&p_h1f, g_h1f);
    cudaGetSymbolAddress((void**)&p_h2f, g_h2f);
    cudaGetSymbolAddress((void**)&p_sqf, g_sqf);
    cudaGetSymbolAddress((void**)&p_Wgh, g_Wgh);
    cudaGetSymbolAddress((void**)&p_Wah, g_Wah);
    cudaGetSymbolAddress((void**)&p_Ygh, g_Ygh);
    cudaGetSymbolAddress((void**)&p_Yah, g_Yah);

    cudaFuncSetAttribute(mma_h<0>, cudaFuncAttributeMaxDynamicSharedMemorySize, SMEM_CV);
    cudaFuncSetAttribute(mma_h<1>, cudaFuncAttributeMaxDynamicSharedMemorySize, SMEM_CV);

    // 0) operand prep (all fp16 single)
    round_half<<<(MSZ / 2 + 255) / 256, 256>>>(x, p_xf, MSZ);
    round_half<<<((long)T1K * Aa * Hh / 2 + 255) / 256, 256>>>(fc1_w, p_f1f, (long)T1K * Aa * Hh);
    round_half<<<((long)T1K * Hh * Aa / 2 + 255) / 256, 256>>>(fc2_w, p_f2f, (long)T1K * Hh * Aa);
    pack_wg<<<((long)NG_PAD * Hh + 255) / 256, 256>>>(c1_w3, c1_w4, c1_w5, c2_w3, c2_w4, c2_w5);
    pack_wa<<<((long)NA_PAD * Hh + 255) / 256, 256>>>(c3_w3, c3_w4, c3_w5);

    // 1) h1 = relu(x @ fc1_w^T + b) -> fp16
    mma_h<1><<<dim3(Aa / 128, M1 / 128, T1K), 256, SMEM_CV>>>(
        p_xf, p_f1f, fc1_b, p_h1f,
        Aa, Hh, 0L, (long)Aa * Hh, (long)Aa, (long)M1 * Aa);

    // 2) h2 = relu(h1 @ fc2_w^T + b) -> fp16
    mma_h<1><<<dim3(Hh / 128, M1 / 128, T1K), 256, SMEM_CV>>>(
        p_h1f, p_f2f, fc2_b, p_h2f,
        Hh, Aa, (long)M1 * Aa, (long)Hh * Aa, (long)Hh, (long)M1 * Hh);

    // 3) squash -> fp16 capsules
    squash_kernel<<<(MSZ + 255) / 256, 256>>>();

    // 4) conv GEMMs (pure fp16)
    mma_h<0><<<dim3(NA_PAD / 128, M1 / 128, 1), 256, SMEM_CV>>>(
        p_sqf, p_Wah, nullptr, p_Yah, NA_PAD, Hh, 0L, 0L, 0L, 0L);
    mma_h<0><<<dim3(NG_PAD / 128, MG / 128, 1), 256, SMEM_CV>>>(
        p_sqf + (long)MSZ, p_Wgh, nullptr, p_Ygh, NG_PAD, Hh, 0L, 0L, 0L, 0L);

    // 5) epilogues
    aspect_epi<<<Bb, 320>>>(c3_b3, c3_b4, c3_b5);
    fca_kernel<<<Bb, 128>>>(fca_w, fca_b);
    gated_epi<<<TnK * Bb, 320>>>(c1_b3, c1_b4, c1_b5, c2_b3, c2_b4, c2_b5);

    // 6) priors + routing
    priors_kernel<<<dim3(Bb, Nn), 72>>>(rw);
    routing_kernel<<<16, 256>>>();

    // 7) residual add
    final_kernel<<<(MSZ + 255) / 256, 256>>>(x, out);
}

// round 10
// speedup vs baseline: 1.9946x; 1.0438x over previous
#include <cuda_runtime.h>
#include <cuda_fp16.h>
#include <math.h>
#include <stdint.h>

// Problem constants
#define Bb   64
#define Ss   128
#define Hh   768
#define Aa   512
#define COn  100
#define TnK  5
#define T1K  6
#define Nn   64
#define SCn  12
#define MSZ  (Bb*Ss*Hh)      // 6291456
#define M1   (Bb*Ss)         // 8192

#define NG_PAD 2432
#define NA_PAD 1280
#define MG     (TnK*M1)      // 40960

// ---------------------------------------------------------------------------
// Scratch (static device globals — allocation-free)
// ---------------------------------------------------------------------------
__device__ __half g_xf[MSZ];
__device__ __half g_f1f[T1K * Aa * Hh];
__device__ __half g_f2f[T1K * Hh * Aa];
__device__ __half g_h1f[T1K * M1 * Aa];
__device__ __half g_h2f[T1K * MSZ];
__device__ __half g_sqf[T1K * MSZ];
__device__ __half g_Wgh[NG_PAD * Hh];
__device__ __half g_Wah[NA_PAD * Hh];
__device__ __half g_Ygh[(long)MG * NG_PAD];
__device__ __half g_Yah[(long)M1 * NA_PAD];
__device__ float g_rwT[(long)Nn * T1K * SCn * 300];   // transposed route_w
__device__ float g_aspf[Bb * 3 * COn];
__device__ float g_asp[Bb * COn];
__device__ float g_z[TnK * Bb * 3 * COn];
__device__ float g_priors[Nn * Bb * T1K * SCn];
__device__ float g_vote[Nn * Bb * SCn];

// ---------------------------------------------------------------------------
// helpers
// ---------------------------------------------------------------------------
__device__ __forceinline__ void mma_fp16(float* c, const uint32_t* a, const uint32_t* b)
{
    asm volatile(
        "mma.sync.aligned.m16n8k16.row.col.f32.f16.f16.f32 "
        "{%0,%1,%2,%3}, {%4,%5,%6,%7}, {%8,%9}, {%0,%1,%2,%3};"
        : "+f"(c[0]), "+f"(c[1]), "+f"(c[2]), "+f"(c[3])
        : "r"(a[0]), "r"(a[1]), "r"(a[2]), "r"(a[3]), "r"(b[0]), "r"(b[1]));
}

__device__ __forceinline__ void cp16(void* sdst, const void* gsrc)
{
    uint32_t s = (uint32_t)__cvta_generic_to_shared(sdst);
    asm volatile("cp.async.cg.shared.global [%0], [%1], 16;" :: "r"(s), "l"(gsrc));
}
#define CP_COMMIT() asm volatile("cp.async.commit_group;" ::: "memory")
#define CP_WAIT0()  asm volatile("cp.async.wait_group 0;" ::: "memory")

#define KC       32
#define RSTR     40
#define MAT_ELE  (128 * RSTR)
#define STG2_ELE (2 * MAT_ELE)
#define SMEM_CV  (2 * STG2_ELE * 2)     // 40960 bytes

// ===========================================================================
// Unified single-term fp16 GEMM (1 MMA/frag), fp16 output.
// ===========================================================================
template<int BIASRELU>
__global__ void __launch_bounds__(256, 2)
mma_h(const __half* __restrict__ A, const __half* __restrict__ B,
      const float* __restrict__ bias, __half* __restrict__ Ch,
      int N, int Kd, long sA, long sW, long sB, long sC)
{
    extern __shared__ __half smh[];
    A += blockIdx.z * sA;
    B += blockIdx.z * sW;
    if (BIASRELU) bias += blockIdx.z * sB;
    long co = blockIdx.z * sC;

    int m0 = blockIdx.y * 128, n0 = blockIdx.x * 128;
    int tid = threadIdx.x, lane = tid & 31, wid = tid >> 5;
    int wm = wid >> 2, wn = wid & 3;
    int gid = lane >> 2, tig = lane & 3;
    int crow = tid >> 2, cch = (tid & 3) * 8;

    auto issue = [&](int c, int st) {
        __half* base = smh + st * STG2_ELE;
        int k0 = c * KC;
        #pragma unroll
        for (int r = 0; r < 2; r++) {
            int row = crow + r * 64;
            long ga = (long)(m0 + row) * Kd + k0 + cch;
            long gb = (long)(n0 + row) * Kd + k0 + cch;
            int so = row * RSTR + cch;
            cp16(base + so,           A + ga);
            cp16(base + MAT_ELE + so, B + gb);
        }
        CP_COMMIT();
    };

    float acc[4][4][4] = {};
    int nch = Kd / KC;

    issue(0, 0);

    for (int c = 0; c < nch; c++) {
        CP_WAIT0();
        __syncthreads();
        if (c + 1 < nch) issue(c + 1, (c + 1) & 1);

        const __half* As = smh + (c & 1) * STG2_ELE;
        const __half* Bs = As + MAT_ELE;

        #pragma unroll
        for (int kk = 0; kk < KC; kk += 16) {
            uint32_t bf[4][2];
            #pragma unroll
            for (int nt = 0; nt < 4; nt++) {
                int off = (wn * 32 + nt * 8 + gid) * RSTR + kk + tig * 2;
                bf[nt][0] = *(const uint32_t*)(Bs + off);
                bf[nt][1] = *(const uint32_t*)(Bs + off + 8);
            }
            #pragma unroll
            for (int mt = 0; mt < 4; mt++) {
                int off = (wm * 64 + mt * 16 + gid) * RSTR + kk + tig * 2;
                uint32_t ah[4];
                ah[0] = *(const uint32_t*)(As + off);
                ah[1] = *(const uint32_t*)(As + off + 8 * RSTR);
                ah[2] = *(const uint32_t*)(As + off + 8);
                ah[3] = *(const uint32_t*)(As + off + 8 * RSTR + 8);
                #pragma unroll
                for (int nt = 0; nt < 4; nt++)
                    mma_fp16(acc[mt][nt], ah, bf[nt]);
            }
        }
        __syncthreads();
    }

    #pragma unroll
    for (int mt = 0; mt < 4; mt++) {
        long m = m0 + wm * 64 + mt * 16 + gid;
        #pragma unroll
        for (int nt = 0; nt < 4; nt++) {
            int col = n0 + wn * 32 + nt * 8 + tig * 2;
            float v00 = acc[mt][nt][0], v01 = acc[mt][nt][1];
            float v10 = acc[mt][nt][2], v11 = acc[mt][nt][3];
            if (BIASRELU) {
                float b0 = bias[col], b1 = bias[col + 1];
                v00 = fmaxf(v00 + b0, 0.f); v01 = fmaxf(v01 + b1, 0.f);
                v10 = fmaxf(v10 + b0, 0.f); v11 = fmaxf(v11 + b1, 0.f);
            }
            *(__half2*)(Ch + co + m * N + col)       = __floats2half2_rn(v00, v01);
            *(__half2*)(Ch + co + (m + 8) * N + col) = __floats2half2_rn(v10, v11);
        }
    }
}

// ===========================================================================
// Operand preparation
// ===========================================================================
__global__ void round_half(const float* __restrict__ in, __half* __restrict__ o, long n)
{
    long i = ((long)blockIdx.x * 256 + threadIdx.x) * 2;
    if (i >= n) return;
    float2 v = *(const float2*)(in + i);
    *(__half2*)(o + i) = __floats2half2_rn(v.x, v.y);
}

__device__ __forceinline__ void decode_kg(int kg, int& K, int& k)
{
    if (kg < 3)      { K = 3; k = kg; }
    else if (kg < 7) { K = 4; k = kg - 3; }
    else             { K = 5; k = kg - 7; }
}

__global__ void pack_wg(const float* __restrict__ c1w3, const float* __restrict__ c1w4,
                        const float* __restrict__ c1w5, const float* __restrict__ c2w3,
                        const float* __restrict__ c2w4, const float* __restrict__ c2w5)
{
    long idx = (long)blockIdx.x * 256 + threadIdx.x;
    if (idx >= (long)NG_PAD * Hh) return;
    int ch = idx / Hh, h = idx % Hh;
    float v = 0.f;
    if (ch < 2400) {
        int kg = ch / 200, r = ch % 200;
        int conv = r / 100, cco = r % 100;
        int K, k; decode_kg(kg, K, k);
        const float* w;
        if (conv == 0) w = (K == 3) ? c1w3 : (K == 4) ? c1w4 : c1w5;
        else           w = (K == 3) ? c2w3 : (K == 4) ? c2w4 : c2w5;
        v = w[(long)cco * Hh * K + h * K + k];
    }
    g_Wgh[idx] = __float2half_rn(v);
}

__global__ void pack_wa(const float* __restrict__ c3w3, const float* __restrict__ c3w4,
                        const float* __restrict__ c3w5)
{
    long idx = (long)blockIdx.x * 256 + threadIdx.x;
    if (idx >= (long)NA_PAD * Hh) return;
    int ch = idx / Hh, h = idx % Hh;
    float v = 0.f;
    if (ch < 1200) {
        int kg = ch / 100, cco = ch % 100;
        int K, k; decode_kg(kg, K, k);
        const float* w = (K == 3) ? c3w3 : (K == 4) ? c3w4 : c3w5;
        v = w[(long)cco * Hh * K + h * K + k];
    }
    g_Wah[idx] = __float2half_rn(v);
}

// transpose route_w: g_rwT[((n*6+i)*12+s)*300 + c] = rw[((n*6+i)*300+c)*12+s]
__global__ void transpose_rw(const float* __restrict__ rw)
{
    long idx = (long)blockIdx.x * 256 + threadIdx.x;
    if (idx >= (long)Nn * T1K * SCn * 300) return;
    int c = idx % 300;
    long row = idx / 300;
    int s = row % 12;
    long ni = row / 12;
    g_rwT[idx] = rw[(ni * 300 + c) * 12 + s];
}

// ===========================================================================
// squash: vectorized, 8 elems/thread
// ===========================================================================
__global__ void squash_kernel()
{
    long i = ((long)blockIdx.x * 256 + threadIdx.x) * 8;
    if (i >= MSZ) return;
    float v[6][8];
    #pragma unroll
    for (int j = 0; j < 6; j++) {
        int src = (j == 0) ? 5 : j - 1;
        uint4 p = *(const uint4*)(g_h2f + (long)src * MSZ + i);
        const __half2* hp = (const __half2*)&p;
        #pragma unroll
        for (int q = 0; q < 4; q++) {
            float2 f = __half22float2(hp[q]);
            v[j][q * 2] = f.x; v[j][q * 2 + 1] = f.y;
        }
    }
    #pragma unroll
    for (int e = 0; e < 8; e++) {
        float sq = 1e-16f;
        #pragma unroll
        for (int j = 0; j < 6; j++) sq += v[j][e] * v[j][e];
        float sc = sqrtf(sq) / (1.f + sq);
        #pragma unroll
        for (int j = 0; j < 6; j++) v[j][e] *= sc;
    }
    #pragma unroll
    for (int j = 0; j < 6; j++) {
        uint4 p;
        __half2* hp = (__half2*)&p;
        #pragma unroll
        for (int q = 0; q < 4; q++)
            hp[q] = __floats2half2_rn(v[j][q * 2], v[j][q * 2 + 1]);
        *(uint4*)(g_sqf + (long)j * MSZ + i) = p;
    }
}

// ===========================================================================
// Fused aspect epilogue + fca. Block per b; 640 threads (600 active).
// ===========================================================================
__global__ void aspect_fca(const float* __restrict__ b3, const float* __restrict__ b4,
                           const float* __restrict__ b5,
                           const float* __restrict__ fw, const float* __restrict__ fb)
{
    __shared__ float red[4 * 300];
    __shared__ float aspf_s[300];
    int b = blockIdx.x, t = threadIdx.x;

    if (t < 600) {
        int lg = t / 150, r = t % 150;
        int g = r / 50, co0 = (r % 50) * 2;
        int K = 3 + g;
        int base = (g == 0) ? 0 : (g == 1) ? 3 : 7;
        int pad = K - 2;
        const float* bias = (g == 0) ? b3 : (g == 1) ? b4 : b5;
        float bb0 = bias[co0], bb1 = bias[co0 + 1];
        int Lout = 125 + K;
        int l0 = lg * 33, l1 = min(Lout, l0 + 33);
        float best0 = 0.f, best1 = 0.f;
        for (int l = l0; l < l1; l++) {
            float s0 = bb0, s1 = bb1;
            #pragma unroll 5
            for (int k = 0; k < K; k++) {
                int ss = l + k - pad;
                if (ss >= 0 && ss < Ss) {
                    __half2 h = *(const __half2*)(g_Yah + ((long)b * Ss + ss) * NA_PAD + (base + k) * 100 + co0);
                    float2 f = __half22float2(h);
                    s0 += f.x; s1 += f.y;
                }
            }
            best0 = fmaxf(best0, s0);
            best1 = fmaxf(best1, s1);
        }
        red[lg * 300 + g * 100 + co0]     = best0;
        red[lg * 300 + g * 100 + co0 + 1] = best1;
    }
    __syncthreads();
    if (t < 300) {
        float m = fmaxf(fmaxf(red[t], red[300 + t]), fmaxf(red[600 + t], red[900 + t]));
        aspf_s[t] = m;
        g_aspf[b * 300 + t] = m;
    }
    __syncthreads();
    if (t < COn) {
        float s = fb[t];
        for (int c = 0; c < 300; c++) s += aspf_s[c] * fw[t * 300 + c];
        g_asp[b * COn + t] = s;
    }
}

// ===========================================================================
// Gated epilogue: half2 channel pairs + 4-way l-split. 640 threads.
// ===========================================================================
__global__ void gated_epi(const float* __restrict__ b13, const float* __restrict__ b14,
                          const float* __restrict__ b15, const float* __restrict__ b23,
                          const float* __restrict__ b24, const float* __restrict__ b25)
{
    __shared__ float red[4 * 300];
    int i = blockIdx.x, t = threadIdx.x;
    int b = i & 63;

    if (t < 600) {
        int lg = t / 150, r = t % 150;
        int g = r / 50, co0 = (r % 50) * 2;
        int K = 3 + g;
        int base = (g == 0) ? 0 : (g == 1) ? 3 : 7;
        const float* bias1 = (g == 0) ? b13 : (g == 1) ? b14 : b15;
        const float* bias2 = (g == 0) ? b23 : (g == 1) ? b24 : b25;
        float c1b0 = bias1[co0], c1b1 = bias1[co0 + 1];
        float c2b0 = bias2[co0]     + g_asp[b * COn + co0];
        float c2b1 = bias2[co0 + 1] + g_asp[b * COn + co0 + 1];
        int Lout = Ss - K + 1;
        int l0 = lg * 32, l1 = min(Lout, l0 + 32);
        float best0 = -1e30f, best1 = -1e30f;
        for (int l = l0; l < l1; l++) {
            float s10 = c1b0, s11 = c1b1, s20 = c2b0, s21 = c2b1;
            #pragma unroll 5
            for (int k = 0; k < K; k++) {
                long row = (long)i * Ss + l + k;
                __half2 ha = *(const __half2*)(g_Ygh + row * NG_PAD + (base + k) * 200 + co0);
                __half2 hb = *(const __half2*)(g_Ygh + row * NG_PAD + (base + k) * 200 + 100 + co0);
                float2 fa = __half22float2(ha);
                float2 fbv = __half22float2(hb);
                s10 += fa.x;  s11 += fa.y;
                s20 += fbv.x; s21 += fbv.y;
            }
            float v0 = tanhf(s10) * fmaxf(s20, 0.f);
            float v1 = tanhf(s11) * fmaxf(s21, 0.f);
            best0 = fmaxf(best0, v0);
            best1 = fmaxf(best1, v1);
        }
        red[lg * 300 + g * 100 + co0]     = best0;
        red[lg * 300 + g * 100 + co0 + 1] = best1;
    }
    __syncthreads();
    if (t < 300)
        g_z[i * 300 + t] = fmaxf(fmaxf(red[t], red[300 + t]), fmaxf(red[600 + t], red[900 + t]));
}

// ===========================================================================
// priors with transposed route_w (contiguous float4 dot)
// ===========================================================================
__global__ void priors_kernel()
{
    __shared__ float cap[1800];
    int b = blockIdx.x, n = blockIdx.y, tid = threadIdx.x;
    for (int idx = tid; idx < 1800; idx += 128) {
        int i = idx / 300, c = idx % 300;
        cap[idx] = (i == 0) ? g_aspf[b * 300 + c] : g_z[((i - 1) * Bb + b) * 300 + c];
    }
    __syncthreads();
    if (tid < 72) {
        int i = tid / 12, s = tid % 12;
        const float4* rp = (const float4*)(g_rwT + ((long)(n * 6 + i) * 12 + s) * 300);
        const float* cp = &cap[i * 300];
        float acc = 0.f;
        #pragma unroll 5
        for (int c4 = 0; c4 < 75; c4++) {
            float4 r4 = rp[c4];
            acc += cp[c4 * 4]     * r4.x + cp[c4 * 4 + 1] * r4.y
                 + cp[c4 * 4 + 2] * r4.z + cp[c4 * 4 + 3] * r4.w;
        }
        g_priors[((n * Bb + b) * 6 + i) * 12 + s] = acc;
    }
}

// ===========================================================================
// routing (unchanged)
// ===========================================================================
__global__ void routing_kernel()
{
    int gid = blockIdx.x * blockDim.x + threadIdx.x;
    if (gid >= Nn * Bb) return;
    float pr[72];
    #pragma unroll
    for (int j = 0; j < 72; j++) pr[j] = g_priors[gid * 72 + j];

    float logits[6] = {0, 0, 0, 0, 0, 0};
    float vote[12];
    #pragma unroll
    for (int it = 0; it < 3; it++) {
        float mx = logits[0];
        #pragma unroll
        for (int i = 1; i < 6; i++) mx = fmaxf(mx, logits[i]);
        float e[6], se = 0.f;
        #pragma unroll
        for (int i = 0; i < 6; i++) { e[i] = expf(logits[i] - mx); se += e[i]; }
        float inv = 1.f / se;
        #pragma unroll
        for (int s = 0; s < 12; s++) {
            float v = 0.f;
            #pragma unroll
            for (int i = 0; i < 6; i++) v += e[i] * pr[i * 12 + s];
            vote[s] = v * inv;
        }
        if (it < 2) {
            float sq = 1e-16f;
            #pragma unroll
            for (int s = 0; s < 12; s++) sq += vote[s] * vote[s];
            float sc = sqrtf(sq) / (1.f + sq);
            #pragma unroll
            for (int i = 0; i < 6; i++) {
                float d = 0.f;
                #pragma unroll
                for (int s = 0; s < 12; s++) d += pr[i * 12 + s] * vote[s];
                logits[i] += d * sc;
            }
        }
    }
    #pragma unroll
    for (int s = 0; s < 12; s++) g_vote[gid * 12 + s] = vote[s];
}

// ===========================================================================
// final residual add, float4 vectorized
// ===========================================================================
__global__ void final_kernel(const float* __restrict__ x, float* __restrict__ out)
{
    long idx = ((long)blockIdx.x * 256 + threadIdx.x) * 4;
    if (idx >= MSZ) return;
    float4 xv = *(const float4*)(x + idx);
    uint2 hp = *(const uint2*)(g_h2f + (long)5 * MSZ + idx);
    const __half2* hh = (const __half2*)&hp;
    float2 h0 = __half22float2(hh[0]);
    float2 h1 = __half22float2(hh[1]);
    int b = (int)(idx / (Ss * Hh));
    int h = (int)(idx % Hh);
    float4 vv = *(const float4*)(g_vote + b * Hh + h);
    float4 o;
    o.x = xv.x + h0.x + vv.x;
    o.y = xv.y + h0.y + vv.y;
    o.z = xv.z + h1.x + vv.z;
    o.w = xv.w + h1.y + vv.w;
    *(float4*)(out + idx) = o;
}

// ===========================================================================
extern "C" void kernel_launch(void* const* d_in, const int* in_sizes, int n_in,
                              void* d_out, int out_size)
{
    const float* x     = (const float*)d_in[0];
    const float* fc1_w = (const float*)d_in[1];
    const float* fc1_b = (const float*)d_in[2];
    const float* fc2_w = (const float*)d_in[3];
    const float* fc2_b = (const float*)d_in[4];
    const float* c1_w3 = (const float*)d_in[5];
    const float* c1_b3 = (const float*)d_in[6];
    const float* c1_w4 = (const float*)d_in[7];
    const float* c1_b4 = (const float*)d_in[8];
    const float* c1_w5 = (const float*)d_in[9];
    const float* c1_b5 = (const float*)d_in[10];
    const float* c2_w3 = (const float*)d_in[11];
    const float* c2_b3 = (const float*)d_in[12];
    const float* c2_w4 = (const float*)d_in[13];
    const float* c2_b4 = (const float*)d_in[14];
    const float* c2_w5 = (const float*)d_in[15];
    const float* c2_b5 = (const float*)d_in[16];
    const float* c3_w3 = (const float*)d_in[17];
    const float* c3_b3 = (const float*)d_in[18];
    const float* c3_w4 = (const float*)d_in[19];
    const float* c3_b4 = (const float*)d_in[20];
    const float* c3_w5 = (const float*)d_in[21];
    const float* c3_b5 = (const float*)d_in[22];
    const float* fca_w = (const float*)d_in[23];
    const float* fca_b = (const float*)d_in[24];
    const float* rw    = (const float*)d_in[25];
    float* out = (float*)d_out;

    __half *p_xf, *p_f1f, *p_f2f, *p_h1f, *p_h2f, *p_sqf, *p_Wgh, *p_Wah, *p_Ygh, *p_Yah;
    cudaGetSymbolAddress((void**)&p_xf,  g_xf);
    cudaGetSymbolAddress((void**)&p_f1f, g_f1f);
    cudaGetSymbolAddress((void**)&p_f2f, g_f2f);
    cudaGetSymbolAddress((void**)&p_h1f, g_h1f);
    cudaGetSymbolAddress((void**)&p_h2f, g_h2f);
    cudaGetSymbolAddress((void**)&p_sqf, g_sqf);
    cudaGetSymbolAddress((void**)&p_Wgh, g_Wgh);
    cudaGetSymbolAddress((void**)&p_Wah, g_Wah);
    cudaGetSymbolAddress((void**)&p_Ygh, g_Ygh);
    cudaGetSymbolAddress((void**)&p_Yah, g_Yah);

    cudaFuncSetAttribute(mma_h<0>, cudaFuncAttributeMaxDynamicSharedMemorySize, SMEM_CV);
    cudaFuncSetAttribute(mma_h<1>, cudaFuncAttributeMaxDynamicSharedMemorySize, SMEM_CV);

    // 0) operand prep
    round_half<<<(MSZ / 2 + 255) / 256, 256>>>(x, p_xf, MSZ);
    round_half<<<((long)T1K * Aa * Hh / 2 + 255) / 256, 256>>>(fc1_w, p_f1f, (long)T1K * Aa * Hh);
    round_half<<<((long)T1K * Hh * Aa / 2 + 255) / 256, 256>>>(fc2_w, p_f2f, (long)T1K * Hh * Aa);
    pack_wg<<<((long)NG_PAD * Hh + 255) / 256, 256>>>(c1_w3, c1_w4, c1_w5, c2_w3, c2_w4, c2_w5);
    pack_wa<<<((long)NA_PAD * Hh + 255) / 256, 256>>>(c3_w3, c3_w4, c3_w5);
    transpose_rw<<<((long)Nn * T1K * SCn * 300 + 255) / 256, 256>>>(rw);

    // 1) h1 = relu(x @ fc1_w^T + b) -> fp16
    mma_h<1><<<dim3(Aa / 128, M1 / 128, T1K), 256, SMEM_CV>>>(
        p_xf, p_f1f, fc1_b, p_h1f,
        Aa, Hh, 0L, (long)Aa * Hh, (long)Aa, (long)M1 * Aa);

    // 2) h2 = relu(h1 @ fc2_w^T + b) -> fp16
    mma_h<1><<<dim3(Hh / 128, M1 / 128, T1K), 256, SMEM_CV>>>(
        p_h1f, p_f2f, fc2_b, p_h2f,
        Hh, Aa, (long)M1 * Aa, (long)Hh * Aa, (long)Hh, (long)M1 * Hh);

    // 3) squash -> fp16 capsules (vectorized)
    squash_kernel<<<(MSZ / 8 + 255) / 256, 256>>>();

    // 4) conv GEMMs
    mma_h<0><<<dim3(NA_PAD / 128, M1 / 128, 1), 256, SMEM_CV>>>(
        p_sqf, p_Wah, nullptr, p_Yah, NA_PAD, Hh, 0L, 0L, 0L, 0L);
    mma_h<0><<<dim3(NG_PAD / 128, MG / 128, 1), 256, SMEM_CV>>>(
        p_sqf + (long)MSZ, p_Wgh, nullptr, p_Ygh, NG_PAD, Hh, 0L, 0L, 0L, 0L);

    // 5) epilogues (parallelized)
    aspect_fca<<<Bb, 640>>>(c3_b3, c3_b4, c3_b5, fca_w, fca_b);
    gated_epi<<<TnK * Bb, 640>>>(c1_b3, c1_b4, c1_b5, c2_b3, c2_b4, c2_b5);

    // 6) priors + routing
    priors_kernel<<<dim3(Bb, Nn), 128>>>();
    routing_kernel<<<16, 256>>>();

    // 7) residual add (vectorized)
    final_kernel<<<(MSZ / 4 + 255) / 256, 256>>>(x, out);
}